// round 1
// baseline (speedup 1.0000x reference)
#include <cuda_runtime.h>
#include <math.h>

// Problem constants
#define B_    2
#define S_    2048
#define H_    2048
#define NH_   16
#define NKV_  4
#define HD_   128
#define M_    (B_ * S_)          // 4096 rows (b*s)
#define QW_   (NH_ * HD_)        // 2048
#define KVW_  (NKV_ * HD_)       // 512
#define NREP_ (NH_ / NKV_)       // 4

// Scratch (static device arrays — no runtime allocation allowed)
__device__ float g_Q[(size_t)M_ * QW_];    // 32 MB
__device__ float g_K[(size_t)M_ * KVW_];   // 8 MB
__device__ float g_V[(size_t)M_ * KVW_];   // 8 MB
__device__ float g_A[(size_t)M_ * QW_];    // 32 MB (attention output)
__device__ float g_cosT[S_ * (HD_ / 2)];
__device__ float g_sinT[S_ * (HD_ / 2)];

// ---------------------------------------------------------------------------
// RoPE tables: built in double precision (safe against fast-math sinf/cosf
// range-reduction error at angles up to 2047), rounded to fp32.
// ---------------------------------------------------------------------------
__global__ void rope_tables_kernel() {
    int idx = blockIdx.x * blockDim.x + threadIdx.x;
    if (idx >= S_ * (HD_ / 2)) return;
    int s = idx >> 6;          // 0..2047
    int j = idx & 63;          // 0..63
    double inv_freq = exp(-((double)j / 64.0) * log(10000.0));
    double ang = (double)s * inv_freq;
    g_cosT[idx] = (float)cos(ang);
    g_sinT[idx] = (float)sin(ang);
}

// ---------------------------------------------------------------------------
// SGEMM with bias: C[M,N] = A[M,K] @ W[N,K]^T + bias[N]
// Tiles: 128x128x16, 256 threads, 8x8 register micro-tile.
// M,N multiples of 128; K multiple of 16 (true for all four calls).
// ---------------------------------------------------------------------------
#define GBM 128
#define GBN 128
#define GBK 16

__global__ __launch_bounds__(256)
void gemm_bias_kernel(const float* __restrict__ A, const float* __restrict__ W,
                      const float* __restrict__ bias, float* __restrict__ C,
                      int M, int N, int K) {
    __shared__ float As[GBK][GBM];
    __shared__ float Bs[GBK][GBN];

    const int bm = blockIdx.y * GBM;
    const int bn = blockIdx.x * GBN;
    const int tid = threadIdx.x;
    const int tr = (tid / 16) * 8;   // row offset in tile
    const int tc = (tid % 16) * 8;   // col offset in tile

    float acc[8][8];
#pragma unroll
    for (int i = 0; i < 8; i++)
#pragma unroll
        for (int j = 0; j < 8; j++) acc[i][j] = 0.f;

    for (int k0 = 0; k0 < K; k0 += GBK) {
        // Load A tile (128x16) as float4, store transposed
#pragma unroll
        for (int l = 0; l < 2; l++) {
            int idx = tid + l * 256;          // 0..511 float4 granules
            int row = idx >> 2;               // 0..127
            int c4  = (idx & 3) << 2;         // 0,4,8,12
            float4 v = *(const float4*)&A[(size_t)(bm + row) * K + k0 + c4];
            As[c4 + 0][row] = v.x; As[c4 + 1][row] = v.y;
            As[c4 + 2][row] = v.z; As[c4 + 3][row] = v.w;
        }
        // Load W tile (128x16), store transposed
#pragma unroll
        for (int l = 0; l < 2; l++) {
            int idx = tid + l * 256;
            int row = idx >> 2;
            int c4  = (idx & 3) << 2;
            float4 v = *(const float4*)&W[(size_t)(bn + row) * K + k0 + c4];
            Bs[c4 + 0][row] = v.x; Bs[c4 + 1][row] = v.y;
            Bs[c4 + 2][row] = v.z; Bs[c4 + 3][row] = v.w;
        }
        __syncthreads();

#pragma unroll
        for (int k = 0; k < GBK; k++) {
            float a[8], b[8];
#pragma unroll
            for (int i = 0; i < 8; i++) a[i] = As[k][tr + i];
#pragma unroll
            for (int j = 0; j < 8; j++) b[j] = Bs[k][tc + j];
#pragma unroll
            for (int i = 0; i < 8; i++)
#pragma unroll
                for (int j = 0; j < 8; j++) acc[i][j] += a[i] * b[j];
        }
        __syncthreads();
    }

#pragma unroll
    for (int i = 0; i < 8; i++) {
#pragma unroll
        for (int j = 0; j < 8; j++) {
            C[(size_t)(bm + tr + i) * N + bn + tc + j] = acc[i][j] + bias[bn + tc + j];
        }
    }
}

// ---------------------------------------------------------------------------
// RoPE apply, in place on (M_, nheads*128) tensor.
// out[j]    = x[j]*cos(f_j*pos)    - x[j+64]*sin(f_j*pos)
// out[j+64] = x[j+64]*cos(f_j*pos) + x[j]   *sin(f_j*pos)
// ---------------------------------------------------------------------------
__global__ void rope_apply_kernel(float* __restrict__ X, int nheads, int total) {
    int idx = blockIdx.x * blockDim.x + threadIdx.x;
    if (idx >= total) return;
    int j = idx & 63;
    int t = idx >> 6;
    int h = t % nheads;
    int row = t / nheads;
    int s = row & (S_ - 1);
    float c  = g_cosT[s * 64 + j];
    float sn = g_sinT[s * 64 + j];
    float* p = X + (size_t)row * (nheads * HD_) + h * HD_;
    float x1 = p[j];
    float x2 = p[j + 64];
    p[j]      = x1 * c - x2 * sn;
    p[j + 64] = x2 * c + x1 * sn;
}

// ---------------------------------------------------------------------------
// Flash attention (non-causal, online softmax), fp32.
// Grid: (S/64, NH, B). Block: 256 threads.
// Per block: 64 query rows, stream keys in tiles of 64.
// smem: Qs[64][128], Kst[128][64] (transposed), Vs[64][128], Ps[64][65]
// ---------------------------------------------------------------------------
#define FBM 64
#define FBN 64
#define FA_SMEM_FLOATS (64*128 + 128*64 + 64*128 + 64*65 + 3*64)
#define FA_SMEM_BYTES  (FA_SMEM_FLOATS * 4)

__global__ __launch_bounds__(256)
void flash_attn_kernel(const float* __restrict__ Q, const float* __restrict__ K,
                       const float* __restrict__ V, float* __restrict__ O) {
    extern __shared__ float sm[];
    float* Qs   = sm;                       // [64][128]
    float* Kst  = Qs  + 64 * 128;           // [128][64]  (dim-major)
    float* Vs   = Kst + 128 * 64;           // [64][128]
    float* Ps   = Vs  + 64 * 128;           // [64][65]
    float* m_sh = Ps  + 64 * 65;            // [64]
    float* l_sh = m_sh + 64;                // [64]
    float* a_sh = l_sh + 64;                // [64]

    const int qtile = blockIdx.x;
    const int h     = blockIdx.y;
    const int b     = blockIdx.z;
    const int kvh   = h / NREP_;
    const int tid   = threadIdx.x;

    const int tr  = (tid / 16) * 4;   // 4 query rows
    const int tc4 = (tid % 16) * 4;   // 4 key cols (scores)
    const int tcO = (tid % 16) * 8;   // 8 output dims

    const float scale = 0.08838834764831845f;  // 1/sqrt(128)

    // Load Q tile
    const size_t qbase = ((size_t)(b * S_ + qtile * FBM)) * QW_ + (size_t)h * HD_;
    for (int i = tid; i < FBM * 32; i += 256) {       // float4 granules
        int r  = i >> 5;
        int c4 = (i & 31) << 2;
        *(float4*)&Qs[r * 128 + c4] = *(const float4*)&Q[qbase + (size_t)r * QW_ + c4];
    }
    if (tid < FBM) { m_sh[tid] = -INFINITY; l_sh[tid] = 0.f; }

    float acc[4][8];
#pragma unroll
    for (int i = 0; i < 4; i++)
#pragma unroll
        for (int j = 0; j < 8; j++) acc[i][j] = 0.f;

    for (int kt = 0; kt < S_ / FBN; kt++) {
        __syncthreads();   // protect smem reuse from previous iteration / Q load
        // Load K tile transposed + V tile
        const size_t kbase = ((size_t)(b * S_ + kt * FBN)) * KVW_ + (size_t)kvh * HD_;
        for (int i = tid; i < FBN * 32; i += 256) {
            int r  = i >> 5;
            int c4 = (i & 31) << 2;
            float4 v = *(const float4*)&K[kbase + (size_t)r * KVW_ + c4];
            Kst[(c4 + 0) * 64 + r] = v.x;
            Kst[(c4 + 1) * 64 + r] = v.y;
            Kst[(c4 + 2) * 64 + r] = v.z;
            Kst[(c4 + 3) * 64 + r] = v.w;
            *(float4*)&Vs[r * 128 + c4] = *(const float4*)&V[kbase + (size_t)r * KVW_ + c4];
        }
        __syncthreads();

        // Scores: s[i][j] = sum_d Qs[tr+i][d] * K[tc4+j][d]
        float s4[4][4];
#pragma unroll
        for (int i = 0; i < 4; i++)
#pragma unroll
            for (int j = 0; j < 4; j++) s4[i][j] = 0.f;

#pragma unroll 4
        for (int d = 0; d < HD_; d++) {
            float4 kv = *(const float4*)&Kst[d * 64 + tc4];
            float q0 = Qs[(tr + 0) * 128 + d];
            float q1 = Qs[(tr + 1) * 128 + d];
            float q2 = Qs[(tr + 2) * 128 + d];
            float q3 = Qs[(tr + 3) * 128 + d];
            s4[0][0] += q0 * kv.x; s4[0][1] += q0 * kv.y; s4[0][2] += q0 * kv.z; s4[0][3] += q0 * kv.w;
            s4[1][0] += q1 * kv.x; s4[1][1] += q1 * kv.y; s4[1][2] += q1 * kv.z; s4[1][3] += q1 * kv.w;
            s4[2][0] += q2 * kv.x; s4[2][1] += q2 * kv.y; s4[2][2] += q2 * kv.z; s4[2][3] += q2 * kv.w;
            s4[3][0] += q3 * kv.x; s4[3][1] += q3 * kv.y; s4[3][2] += q3 * kv.z; s4[3][3] += q3 * kv.w;
        }
#pragma unroll
        for (int i = 0; i < 4; i++)
#pragma unroll
            for (int j = 0; j < 4; j++)
                Ps[(tr + i) * 65 + tc4 + j] = s4[i][j] * scale;
        __syncthreads();

        // Online softmax per row (threads 0..63, one row each)
        if (tid < FBM) {
            float mold = m_sh[tid];
            float mx = mold;
            const float* prow = &Ps[tid * 65];
#pragma unroll 8
            for (int k = 0; k < FBN; k++) mx = fmaxf(mx, prow[k]);
            float alpha = expf(mold - mx);
            float sum = 0.f;
            float* prw = &Ps[tid * 65];
#pragma unroll 8
            for (int k = 0; k < FBN; k++) {
                float p = expf(prw[k] - mx);
                prw[k] = p;
                sum += p;
            }
            l_sh[tid] = l_sh[tid] * alpha + sum;
            m_sh[tid] = mx;
            a_sh[tid] = alpha;
        }
        __syncthreads();

        // Rescale accumulators, then acc += P @ V
        float al[4];
#pragma unroll
        for (int i = 0; i < 4; i++) al[i] = a_sh[tr + i];
#pragma unroll
        for (int i = 0; i < 4; i++)
#pragma unroll
            for (int j = 0; j < 8; j++) acc[i][j] *= al[i];

#pragma unroll 4
        for (int k = 0; k < FBN; k++) {
            float p0 = Ps[(tr + 0) * 65 + k];
            float p1 = Ps[(tr + 1) * 65 + k];
            float p2 = Ps[(tr + 2) * 65 + k];
            float p3 = Ps[(tr + 3) * 65 + k];
            float4 v0 = *(const float4*)&Vs[k * 128 + tcO];
            float4 v1 = *(const float4*)&Vs[k * 128 + tcO + 4];
            acc[0][0] += p0 * v0.x; acc[0][1] += p0 * v0.y; acc[0][2] += p0 * v0.z; acc[0][3] += p0 * v0.w;
            acc[0][4] += p0 * v1.x; acc[0][5] += p0 * v1.y; acc[0][6] += p0 * v1.z; acc[0][7] += p0 * v1.w;
            acc[1][0] += p1 * v0.x; acc[1][1] += p1 * v0.y; acc[1][2] += p1 * v0.z; acc[1][3] += p1 * v0.w;
            acc[1][4] += p1 * v1.x; acc[1][5] += p1 * v1.y; acc[1][6] += p1 * v1.z; acc[1][7] += p1 * v1.w;
            acc[2][0] += p2 * v0.x; acc[2][1] += p2 * v0.y; acc[2][2] += p2 * v0.z; acc[2][3] += p2 * v0.w;
            acc[2][4] += p2 * v1.x; acc[2][5] += p2 * v1.y; acc[2][6] += p2 * v1.z; acc[2][7] += p2 * v1.w;
            acc[3][0] += p3 * v0.x; acc[3][1] += p3 * v0.y; acc[3][2] += p3 * v0.z; acc[3][3] += p3 * v0.w;
            acc[3][4] += p3 * v1.x; acc[3][5] += p3 * v1.y; acc[3][6] += p3 * v1.z; acc[3][7] += p3 * v1.w;
        }
    }
    __syncthreads();

    // Normalize and write out
    const size_t obase = ((size_t)(b * S_ + qtile * FBM)) * QW_ + (size_t)h * HD_;
#pragma unroll
    for (int i = 0; i < 4; i++) {
        float inv = 1.f / (l_sh[tr + i] + 1e-10f);
#pragma unroll
        for (int j = 0; j < 8; j++) {
            O[obase + (size_t)(tr + i) * QW_ + tcO + j] = acc[i][j] * inv;
        }
    }
}

// ---------------------------------------------------------------------------
// Launch
// ---------------------------------------------------------------------------
extern "C" void kernel_launch(void* const* d_in, const int* in_sizes, int n_in,
                              void* d_out, int out_size) {
    const float* X   = (const float*)d_in[0];
    const float* q_w = (const float*)d_in[1];
    const float* q_b = (const float*)d_in[2];
    const float* k_w = (const float*)d_in[3];
    const float* k_b = (const float*)d_in[4];
    const float* v_w = (const float*)d_in[5];
    const float* v_b = (const float*)d_in[6];
    const float* o_w = (const float*)d_in[7];
    const float* o_b = (const float*)d_in[8];
    float* out = (float*)d_out;

    float *pQ, *pK, *pV, *pA;
    cudaGetSymbolAddress((void**)&pQ, g_Q);
    cudaGetSymbolAddress((void**)&pK, g_K);
    cudaGetSymbolAddress((void**)&pV, g_V);
    cudaGetSymbolAddress((void**)&pA, g_A);

    cudaFuncSetAttribute(flash_attn_kernel,
                         cudaFuncAttributeMaxDynamicSharedMemorySize, FA_SMEM_BYTES);

    // RoPE tables
    {
        int total = S_ * (HD_ / 2);
        rope_tables_kernel<<<(total + 255) / 256, 256>>>();
    }

    // Projections
    gemm_bias_kernel<<<dim3(QW_ / GBN, M_ / GBM), 256>>>(X, q_w, q_b, pQ, M_, QW_, H_);
    gemm_bias_kernel<<<dim3(KVW_ / GBN, M_ / GBM), 256>>>(X, k_w, k_b, pK, M_, KVW_, H_);
    gemm_bias_kernel<<<dim3(KVW_ / GBN, M_ / GBM), 256>>>(X, v_w, v_b, pV, M_, KVW_, H_);

    // RoPE on Q and K
    {
        int totQ = M_ * NH_ * 64;
        rope_apply_kernel<<<(totQ + 255) / 256, 256>>>(pQ, NH_, totQ);
        int totK = M_ * NKV_ * 64;
        rope_apply_kernel<<<(totK + 255) / 256, 256>>>(pK, NKV_, totK);
    }

    // Attention
    flash_attn_kernel<<<dim3(S_ / FBM, NH_, B_), 256, FA_SMEM_BYTES>>>(pQ, pK, pV, pA);

    // Output projection
    gemm_bias_kernel<<<dim3(H_ / GBN, M_ / GBM), 256>>>(pA, o_w, o_b, out, M_, H_, H_);
}

// round 2
// speedup vs baseline: 2.4949x; 2.4949x over previous
#include <cuda_runtime.h>
#include <cuda_bf16.h>
#include <math.h>
#include <stdint.h>

// Problem constants
#define B_    2
#define S_    2048
#define H_    2048
#define NH_   16
#define NKV_  4
#define HD_   128
#define M_    (B_ * S_)          // 4096
#define QW_   (NH_ * HD_)        // 2048
#define KVW_  (NKV_ * HD_)       // 512
#define NREP_ (NH_ / NKV_)       // 4

// Scratch
__device__ float g_Q[(size_t)M_ * QW_];
__device__ float g_K[(size_t)M_ * KVW_];
__device__ float g_V[(size_t)M_ * KVW_];
__device__ float g_A[(size_t)M_ * QW_];
__device__ float g_cosT[S_ * 64];
__device__ float g_sinT[S_ * 64];

// ---------------------------------------------------------------------------
// Helpers: ldmatrix / mma / bf16 split
// ---------------------------------------------------------------------------
__device__ __forceinline__ uint32_t smem_u32(const void* p) {
    return (uint32_t)__cvta_generic_to_shared(p);
}
__device__ __forceinline__ void ldsm_x4(uint32_t* r, uint32_t a) {
    asm volatile("ldmatrix.sync.aligned.m8n8.x4.shared.b16 {%0,%1,%2,%3},[%4];"
        : "=r"(r[0]), "=r"(r[1]), "=r"(r[2]), "=r"(r[3]) : "r"(a));
}
__device__ __forceinline__ void ldsm_x4_t(uint32_t* r, uint32_t a) {
    asm volatile("ldmatrix.sync.aligned.m8n8.x4.trans.shared.b16 {%0,%1,%2,%3},[%4];"
        : "=r"(r[0]), "=r"(r[1]), "=r"(r[2]), "=r"(r[3]) : "r"(a));
}
__device__ __forceinline__ void mma_bf16(float* c, const uint32_t* a, uint32_t b0, uint32_t b1) {
    asm volatile(
        "mma.sync.aligned.m16n8k16.row.col.f32.bf16.bf16.f32 "
        "{%0,%1,%2,%3},{%4,%5,%6,%7},{%8,%9},{%0,%1,%2,%3};"
        : "+f"(c[0]), "+f"(c[1]), "+f"(c[2]), "+f"(c[3])
        : "r"(a[0]), "r"(a[1]), "r"(a[2]), "r"(a[3]), "r"(b0), "r"(b1));
}
__device__ __forceinline__ uint32_t pack2(__nv_bfloat16 a, __nv_bfloat16 b) {
    uint16_t ua = *reinterpret_cast<uint16_t*>(&a);
    uint16_t ub = *reinterpret_cast<uint16_t*>(&b);
    return (uint32_t)ua | ((uint32_t)ub << 16);
}
// split (x,y) into hi/lo bf16 pairs packed as b32
__device__ __forceinline__ void split2(float x, float y, uint32_t& hi, uint32_t& lo) {
    __nv_bfloat16 hx = __float2bfloat16(x), hy = __float2bfloat16(y);
    float rx = x - __bfloat162float(hx);
    float ry = y - __bfloat162float(hy);
    hi = pack2(hx, hy);
    lo = pack2(__float2bfloat16(rx), __float2bfloat16(ry));
}

// ---------------------------------------------------------------------------
// RoPE tables (double precision build)
// ---------------------------------------------------------------------------
__global__ void rope_tables_kernel() {
    int idx = blockIdx.x * blockDim.x + threadIdx.x;
    if (idx >= S_ * 64) return;
    int s = idx >> 6;
    int j = idx & 63;
    double inv_freq = exp(-((double)j / 64.0) * log(10000.0));
    double ang = (double)s * inv_freq;
    g_cosT[idx] = (float)cos(ang);
    g_sinT[idx] = (float)sin(ang);
}

__global__ void rope_apply_kernel(float* __restrict__ X, int nheads, int total) {
    int idx = blockIdx.x * blockDim.x + threadIdx.x;
    if (idx >= total) return;
    int j = idx & 63;
    int t = idx >> 6;
    int h = t % nheads;
    int row = t / nheads;
    int s = row & (S_ - 1);
    float c  = g_cosT[s * 64 + j];
    float sn = g_sinT[s * 64 + j];
    float* p = X + (size_t)row * (nheads * HD_) + h * HD_;
    float x1 = p[j];
    float x2 = p[j + 64];
    p[j]      = x1 * c - x2 * sn;
    p[j + 64] = x2 * c + x1 * sn;
}

// ---------------------------------------------------------------------------
// GEMM (bf16x3 tensor-core): C[M,N] = A[M,K] @ W[N,K]^T + bias
// BM=BN=128, BK=32, 256 threads (8 warps, 2x4), warp tile 64x32
// ---------------------------------------------------------------------------
#define BM 128
#define BN 128
#define BK 32
#define SA 40                    // smem row stride in bf16 (32 + 8 pad)
#define STILE (BM * SA)          // 5120 bf16 per tile buffer
#define GEMM_SMEM (8 * STILE * 2)  // 8 buffers (Ah/Al/Bh/Bl x2 stages) = 81920 B

__global__ __launch_bounds__(256, 1)
void gemm_bias_tc(const float* __restrict__ A, const float* __restrict__ W,
                  const float* __restrict__ bias, float* __restrict__ C,
                  int M, int N, int K) {
    extern __shared__ __nv_bfloat16 smg[];
    __nv_bfloat16* Ah = smg;
    __nv_bfloat16* Al = Ah + 2 * STILE;
    __nv_bfloat16* Bh = Al + 2 * STILE;
    __nv_bfloat16* Bl = Bh + 2 * STILE;

    const int tid = threadIdx.x;
    const int lane = tid & 31, wid = tid >> 5;
    const int wm = wid >> 2, wn = wid & 3;
    const int bm = blockIdx.y * BM, bn = blockIdx.x * BN;

    float acc[4][4][4];
#pragma unroll
    for (int i = 0; i < 4; i++)
#pragma unroll
        for (int j = 0; j < 4; j++)
#pragma unroll
            for (int k = 0; k < 4; k++) acc[i][j][k] = 0.f;

    // ldmatrix per-lane offsets
    const int arow = (lane & 7) + ((lane >> 3) & 1) * 8;   // A: j&1 -> row+8
    const int acol = ((lane >> 4) & 1) * 8;                // A: j>>1 -> k+8
    const int brow = (lane & 7) + ((lane >> 4) & 1) * 8;   // B: j>>1 -> n+8
    const int bcol = ((lane >> 3) & 1) * 8;                // B: j&1 -> k+8

    float4 ra[4], rb[4];
    const int nIter = K / BK;

    // prologue: load + convert tile 0 into stage 0
#pragma unroll
    for (int i = 0; i < 4; i++) {
        int idx = i * 256 + tid, m = idx >> 3, kq = idx & 7;
        ra[i] = *(const float4*)&A[(size_t)(bm + m) * K + kq * 4];
        rb[i] = *(const float4*)&W[(size_t)(bn + m) * K + kq * 4];
    }
#pragma unroll
    for (int i = 0; i < 4; i++) {
        int idx = i * 256 + tid, m = idx >> 3, kq = idx & 7;
        uint32_t h0, h1, l0, l1;
        split2(ra[i].x, ra[i].y, h0, l0); split2(ra[i].z, ra[i].w, h1, l1);
        *(uint32_t*)&Ah[m * SA + kq * 4] = h0; *(uint32_t*)&Ah[m * SA + kq * 4 + 2] = h1;
        *(uint32_t*)&Al[m * SA + kq * 4] = l0; *(uint32_t*)&Al[m * SA + kq * 4 + 2] = l1;
        split2(rb[i].x, rb[i].y, h0, l0); split2(rb[i].z, rb[i].w, h1, l1);
        *(uint32_t*)&Bh[m * SA + kq * 4] = h0; *(uint32_t*)&Bh[m * SA + kq * 4 + 2] = h1;
        *(uint32_t*)&Bl[m * SA + kq * 4] = l0; *(uint32_t*)&Bl[m * SA + kq * 4 + 2] = l1;
    }
    __syncthreads();

    for (int t = 0; t < nIter; t++) {
        const int buf = t & 1;
        if (t + 1 < nIter) {
            int k0 = (t + 1) * BK;
#pragma unroll
            for (int i = 0; i < 4; i++) {
                int idx = i * 256 + tid, m = idx >> 3, kq = idx & 7;
                ra[i] = *(const float4*)&A[(size_t)(bm + m) * K + k0 + kq * 4];
                rb[i] = *(const float4*)&W[(size_t)(bn + m) * K + k0 + kq * 4];
            }
        }
        const __nv_bfloat16* pAh = Ah + buf * STILE;
        const __nv_bfloat16* pAl = Al + buf * STILE;
        const __nv_bfloat16* pBh = Bh + buf * STILE;
        const __nv_bfloat16* pBl = Bl + buf * STILE;

#pragma unroll
        for (int kk = 0; kk < BK; kk += 16) {
            uint32_t fah[4][4], fal[4][4], fbh[2][4], fbl[2][4];
#pragma unroll
            for (int mt = 0; mt < 4; mt++) {
                int r = wm * 64 + mt * 16 + arow;
                ldsm_x4(fah[mt], smem_u32(pAh + r * SA + kk + acol));
                ldsm_x4(fal[mt], smem_u32(pAl + r * SA + kk + acol));
            }
#pragma unroll
            for (int np = 0; np < 2; np++) {
                int r = wn * 32 + np * 16 + brow;
                ldsm_x4(fbh[np], smem_u32(pBh + r * SA + kk + bcol));
                ldsm_x4(fbl[np], smem_u32(pBl + r * SA + kk + bcol));
            }
#pragma unroll
            for (int mt = 0; mt < 4; mt++) {
#pragma unroll
                for (int nt = 0; nt < 4; nt++) {
                    int np = nt >> 1, hf = (nt & 1) * 2;
                    mma_bf16(acc[mt][nt], fah[mt], fbh[np][hf], fbh[np][hf + 1]);
                    mma_bf16(acc[mt][nt], fal[mt], fbh[np][hf], fbh[np][hf + 1]);
                    mma_bf16(acc[mt][nt], fah[mt], fbl[np][hf], fbl[np][hf + 1]);
                }
            }
        }

        if (t + 1 < nIter) {
            const int nb = (t + 1) & 1;
            __nv_bfloat16* qAh = Ah + nb * STILE;
            __nv_bfloat16* qAl = Al + nb * STILE;
            __nv_bfloat16* qBh = Bh + nb * STILE;
            __nv_bfloat16* qBl = Bl + nb * STILE;
#pragma unroll
            for (int i = 0; i < 4; i++) {
                int idx = i * 256 + tid, m = idx >> 3, kq = idx & 7;
                uint32_t h0, h1, l0, l1;
                split2(ra[i].x, ra[i].y, h0, l0); split2(ra[i].z, ra[i].w, h1, l1);
                *(uint32_t*)&qAh[m * SA + kq * 4] = h0; *(uint32_t*)&qAh[m * SA + kq * 4 + 2] = h1;
                *(uint32_t*)&qAl[m * SA + kq * 4] = l0; *(uint32_t*)&qAl[m * SA + kq * 4 + 2] = l1;
                split2(rb[i].x, rb[i].y, h0, l0); split2(rb[i].z, rb[i].w, h1, l1);
                *(uint32_t*)&qBh[m * SA + kq * 4] = h0; *(uint32_t*)&qBh[m * SA + kq * 4 + 2] = h1;
                *(uint32_t*)&qBl[m * SA + kq * 4] = l0; *(uint32_t*)&qBl[m * SA + kq * 4 + 2] = l1;
            }
        }
        __syncthreads();
    }

    // epilogue
    const int g = lane >> 2, c2 = (lane & 3) * 2;
#pragma unroll
    for (int mt = 0; mt < 4; mt++) {
        int row = bm + wm * 64 + mt * 16 + g;
#pragma unroll
        for (int nt = 0; nt < 4; nt++) {
            int col = bn + wn * 32 + nt * 8 + c2;
            float b0 = bias[col], b1 = bias[col + 1];
            *(float2*)&C[(size_t)row * N + col] =
                make_float2(acc[mt][nt][0] + b0, acc[mt][nt][1] + b1);
            *(float2*)&C[(size_t)(row + 8) * N + col] =
                make_float2(acc[mt][nt][2] + b0, acc[mt][nt][3] + b1);
        }
    }
}

// ---------------------------------------------------------------------------
// Flash attention (bf16x3 tensor-core, online softmax)
// Per CTA: 64 q-rows x one head; key tiles of 64. 256 threads (8 warps 2x4).
// ---------------------------------------------------------------------------
#define QS 136   // bf16 stride for Q/K/V tiles (128 + 8)
#define PS 72    // bf16 stride for P tiles (64 + 8)
#define SSW 68   // f32 stride for raw scores
#define FA_SMEM (6*64*QS*2 + 2*64*PS*2 + 64*SSW*4 + 3*64*4 + 2*256*4)  // 143104

__global__ __launch_bounds__(256, 1)
void flash_tc(const float* __restrict__ Q, const float* __restrict__ K,
              const float* __restrict__ V, float* __restrict__ O) {
    extern __shared__ char smraw[];
    __nv_bfloat16* Qh = (__nv_bfloat16*)smraw;
    __nv_bfloat16* Ql = Qh + 64 * QS;
    __nv_bfloat16* Kh = Ql + 64 * QS;
    __nv_bfloat16* Kl = Kh + 64 * QS;
    __nv_bfloat16* Vh = Kl + 64 * QS;
    __nv_bfloat16* Vl = Vh + 64 * QS;
    __nv_bfloat16* Ph = Vl + 64 * QS;
    __nv_bfloat16* Pl = Ph + 64 * PS;
    float* Ss   = (float*)(Pl + 64 * PS);
    float* m_sh = Ss + 64 * SSW;
    float* l_sh = m_sh + 64;
    float* a_sh = l_sh + 64;
    float* rmax = a_sh + 64;     // [4][64]
    float* rsum = rmax + 256;    // [4][64]

    const int tid = threadIdx.x, lane = tid & 31, wid = tid >> 5;
    const int wm = wid >> 2, wn = wid & 3;
    const int qt = blockIdx.x, h = blockIdx.y, b = blockIdx.z;
    const int kvh = h / NREP_;
    const float scale = 0.08838834764831845f;

    const int g = lane >> 2, c2 = (lane & 3) * 2;
    const int arow = (lane & 7) + ((lane >> 3) & 1) * 8;
    const int acol = ((lane >> 4) & 1) * 8;
    const int brow = (lane & 7) + ((lane >> 4) & 1) * 8;
    const int bcol = ((lane >> 3) & 1) * 8;
    // trans (V): row = key, col = d
    const int vrow = (lane & 7) + ((lane >> 3) & 1) * 8;
    const int vcol = ((lane >> 4) & 1) * 8;

    // Load Q tile once
    {
        const size_t qb = ((size_t)(b * S_ + qt * 64)) * QW_ + (size_t)h * HD_;
#pragma unroll
        for (int i = 0; i < 8; i++) {
            int idx = i * 256 + tid;
            int r = idx >> 5, q4 = (idx & 31) * 4;
            float4 v = *(const float4*)&Q[qb + (size_t)r * QW_ + q4];
            uint32_t h0, h1, l0, l1;
            split2(v.x, v.y, h0, l0); split2(v.z, v.w, h1, l1);
            *(uint32_t*)&Qh[r * QS + q4] = h0; *(uint32_t*)&Qh[r * QS + q4 + 2] = h1;
            *(uint32_t*)&Ql[r * QS + q4] = l0; *(uint32_t*)&Ql[r * QS + q4 + 2] = l1;
        }
        if (tid < 64) { m_sh[tid] = -INFINITY; l_sh[tid] = 0.f; }
    }

    float acco[2][4][4];
#pragma unroll
    for (int i = 0; i < 2; i++)
#pragma unroll
        for (int j = 0; j < 4; j++)
#pragma unroll
            for (int k = 0; k < 4; k++) acco[i][j][k] = 0.f;

    for (int kt = 0; kt < S_ / 64; kt++) {
        __syncthreads();
        // Load K,V tiles
        const size_t kb = ((size_t)(b * S_ + kt * 64)) * KVW_ + (size_t)kvh * HD_;
#pragma unroll
        for (int i = 0; i < 8; i++) {
            int idx = i * 256 + tid;
            int r = idx >> 5, q4 = (idx & 31) * 4;
            float4 kv = *(const float4*)&K[kb + (size_t)r * KVW_ + q4];
            float4 vv = *(const float4*)&V[kb + (size_t)r * KVW_ + q4];
            uint32_t h0, h1, l0, l1;
            split2(kv.x, kv.y, h0, l0); split2(kv.z, kv.w, h1, l1);
            *(uint32_t*)&Kh[r * QS + q4] = h0; *(uint32_t*)&Kh[r * QS + q4 + 2] = h1;
            *(uint32_t*)&Kl[r * QS + q4] = l0; *(uint32_t*)&Kl[r * QS + q4 + 2] = l1;
            split2(vv.x, vv.y, h0, l0); split2(vv.z, vv.w, h1, l1);
            *(uint32_t*)&Vh[r * QS + q4] = h0; *(uint32_t*)&Vh[r * QS + q4 + 2] = h1;
            *(uint32_t*)&Vl[r * QS + q4] = l0; *(uint32_t*)&Vl[r * QS + q4 + 2] = l1;
        }
        __syncthreads();

        // ---- S = Q @ K^T (warp tile 32x16) ----
        float sac[2][2][4];
#pragma unroll
        for (int i = 0; i < 2; i++)
#pragma unroll
            for (int j = 0; j < 2; j++)
#pragma unroll
                for (int k = 0; k < 4; k++) sac[i][j][k] = 0.f;

#pragma unroll
        for (int kk = 0; kk < 128; kk += 16) {
            uint32_t qh[2][4], ql[2][4], kh[4], kl[4];
#pragma unroll
            for (int mt = 0; mt < 2; mt++) {
                int r = wm * 32 + mt * 16 + arow;
                ldsm_x4(qh[mt], smem_u32(Qh + r * QS + kk + acol));
                ldsm_x4(ql[mt], smem_u32(Ql + r * QS + kk + acol));
            }
            {
                int r = wn * 16 + brow;
                ldsm_x4(kh, smem_u32(Kh + r * QS + kk + bcol));
                ldsm_x4(kl, smem_u32(Kl + r * QS + kk + bcol));
            }
#pragma unroll
            for (int mt = 0; mt < 2; mt++) {
#pragma unroll
                for (int nt = 0; nt < 2; nt++) {
                    int hf = nt * 2;
                    mma_bf16(sac[mt][nt], qh[mt], kh[hf], kh[hf + 1]);
                    mma_bf16(sac[mt][nt], ql[mt], kh[hf], kh[hf + 1]);
                    mma_bf16(sac[mt][nt], qh[mt], kl[hf], kl[hf + 1]);
                }
            }
        }
        // write scaled scores
#pragma unroll
        for (int mt = 0; mt < 2; mt++) {
#pragma unroll
            for (int nt = 0; nt < 2; nt++) {
                int r0 = wm * 32 + mt * 16 + g;
                int cc = wn * 16 + nt * 8 + c2;
                Ss[r0 * SSW + cc]           = sac[mt][nt][0] * scale;
                Ss[r0 * SSW + cc + 1]       = sac[mt][nt][1] * scale;
                Ss[(r0 + 8) * SSW + cc]     = sac[mt][nt][2] * scale;
                Ss[(r0 + 8) * SSW + cc + 1] = sac[mt][nt][3] * scale;
            }
        }
        __syncthreads();

        // ---- softmax (4 segments of 16 per row) ----
        {
            int r = tid & 63, seg = tid >> 6;
            const float* sr = Ss + r * SSW + seg * 16;
            float mx = -INFINITY;
#pragma unroll
            for (int i = 0; i < 16; i++) mx = fmaxf(mx, sr[i]);
            rmax[seg * 64 + r] = mx;
            __syncthreads();
            float mo = m_sh[r];
            float mn = fmaxf(fmaxf(fmaxf(rmax[r], rmax[64 + r]),
                                   fmaxf(rmax[128 + r], rmax[192 + r])), mo);
            float sum = 0.f;
#pragma unroll
            for (int i = 0; i < 16; i++) {
                float p = expf(sr[i] - mn);
                __nv_bfloat16 ph = __float2bfloat16(p);
                Ph[r * PS + seg * 16 + i] = ph;
                Pl[r * PS + seg * 16 + i] = __float2bfloat16(p - __bfloat162float(ph));
                sum += p;
            }
            rsum[seg * 64 + r] = sum;
            __syncthreads();
            if (tid < 64) {
                float al = expf(mo - mn);
                l_sh[r] = l_sh[r] * al + rsum[r] + rsum[64 + r] + rsum[128 + r] + rsum[192 + r];
                m_sh[r] = mn;
                a_sh[r] = al;
            }
            __syncthreads();
        }

        // rescale accumulators
#pragma unroll
        for (int mt = 0; mt < 2; mt++) {
            float a0 = a_sh[wm * 32 + mt * 16 + g];
            float a1 = a_sh[wm * 32 + mt * 16 + 8 + g];
#pragma unroll
            for (int nt = 0; nt < 4; nt++) {
                acco[mt][nt][0] *= a0; acco[mt][nt][1] *= a0;
                acco[mt][nt][2] *= a1; acco[mt][nt][3] *= a1;
            }
        }

        // ---- O += P @ V (warp tile 32x32, K=64 keys) ----
#pragma unroll
        for (int kk = 0; kk < 64; kk += 16) {
            uint32_t ph_[2][4], pl_[2][4], vh_[2][4], vl_[2][4];
#pragma unroll
            for (int mt = 0; mt < 2; mt++) {
                int r = wm * 32 + mt * 16 + arow;
                ldsm_x4(ph_[mt], smem_u32(Ph + r * PS + kk + acol));
                ldsm_x4(pl_[mt], smem_u32(Pl + r * PS + kk + acol));
            }
#pragma unroll
            for (int np = 0; np < 2; np++) {
                int nb = wn * 32 + np * 16;
                int vr = kk + vrow;
                ldsm_x4_t(vh_[np], smem_u32(Vh + vr * QS + nb + vcol));
                ldsm_x4_t(vl_[np], smem_u32(Vl + vr * QS + nb + vcol));
            }
#pragma unroll
            for (int mt = 0; mt < 2; mt++) {
#pragma unroll
                for (int nt = 0; nt < 4; nt++) {
                    int np = nt >> 1, hf = (nt & 1) * 2;
                    mma_bf16(acco[mt][nt], ph_[mt], vh_[np][hf], vh_[np][hf + 1]);
                    mma_bf16(acco[mt][nt], pl_[mt], vh_[np][hf], vh_[np][hf + 1]);
                    mma_bf16(acco[mt][nt], ph_[mt], vl_[np][hf], vl_[np][hf + 1]);
                }
            }
        }
    }

    // epilogue: normalize + write
    const size_t ob = ((size_t)(b * S_ + qt * 64)) * QW_ + (size_t)h * HD_;
#pragma unroll
    for (int mt = 0; mt < 2; mt++) {
        int r0 = wm * 32 + mt * 16 + g;
        float inv0 = 1.f / (l_sh[r0] + 1e-10f);
        float inv1 = 1.f / (l_sh[r0 + 8] + 1e-10f);
#pragma unroll
        for (int nt = 0; nt < 4; nt++) {
            int col = wn * 32 + nt * 8 + c2;
            *(float2*)&O[ob + (size_t)r0 * QW_ + col] =
                make_float2(acco[mt][nt][0] * inv0, acco[mt][nt][1] * inv0);
            *(float2*)&O[ob + (size_t)(r0 + 8) * QW_ + col] =
                make_float2(acco[mt][nt][2] * inv1, acco[mt][nt][3] * inv1);
        }
    }
}

// ---------------------------------------------------------------------------
// Launch
// ---------------------------------------------------------------------------
extern "C" void kernel_launch(void* const* d_in, const int* in_sizes, int n_in,
                              void* d_out, int out_size) {
    const float* X   = (const float*)d_in[0];
    const float* q_w = (const float*)d_in[1];
    const float* q_b = (const float*)d_in[2];
    const float* k_w = (const float*)d_in[3];
    const float* k_b = (const float*)d_in[4];
    const float* v_w = (const float*)d_in[5];
    const float* v_b = (const float*)d_in[6];
    const float* o_w = (const float*)d_in[7];
    const float* o_b = (const float*)d_in[8];
    float* out = (float*)d_out;

    float *pQ, *pK, *pV, *pA;
    cudaGetSymbolAddress((void**)&pQ, g_Q);
    cudaGetSymbolAddress((void**)&pK, g_K);
    cudaGetSymbolAddress((void**)&pV, g_V);
    cudaGetSymbolAddress((void**)&pA, g_A);

    cudaFuncSetAttribute(gemm_bias_tc, cudaFuncAttributeMaxDynamicSharedMemorySize, GEMM_SMEM);
    cudaFuncSetAttribute(flash_tc, cudaFuncAttributeMaxDynamicSharedMemorySize, FA_SMEM);

    // RoPE tables
    {
        int total = S_ * 64;
        rope_tables_kernel<<<(total + 255) / 256, 256>>>();
    }

    // Projections
    gemm_bias_tc<<<dim3(QW_ / BN, M_ / BM), 256, GEMM_SMEM>>>(X, q_w, q_b, pQ, M_, QW_, H_);
    gemm_bias_tc<<<dim3(KVW_ / BN, M_ / BM), 256, GEMM_SMEM>>>(X, k_w, k_b, pK, M_, KVW_, H_);
    gemm_bias_tc<<<dim3(KVW_ / BN, M_ / BM), 256, GEMM_SMEM>>>(X, v_w, v_b, pV, M_, KVW_, H_);

    // RoPE
    {
        int totQ = M_ * NH_ * 64;
        rope_apply_kernel<<<(totQ + 255) / 256, 256>>>(pQ, NH_, totQ);
        int totK = M_ * NKV_ * 64;
        rope_apply_kernel<<<(totK + 255) / 256, 256>>>(pK, NKV_, totK);
    }

    // Attention
    flash_tc<<<dim3(S_ / 64, NH_, B_), 256, FA_SMEM>>>(pQ, pK, pV, pA);

    // Output projection
    gemm_bias_tc<<<dim3(H_ / BN, M_ / BM), 256, GEMM_SMEM>>>(pA, o_w, o_b, out, M_, H_, H_);
}

// round 3
// speedup vs baseline: 3.7302x; 1.4951x over previous
#include <cuda_runtime.h>
#include <cuda_bf16.h>
#include <math.h>
#include <stdint.h>

typedef __nv_bfloat16 bf16;

// Problem constants
#define B_    2
#define S_    2048
#define H_    2048
#define NH_   16
#define NKV_  4
#define HD_   128
#define M_    (B_ * S_)          // 4096
#define QW_   (NH_ * HD_)        // 2048
#define KVW_  (NKV_ * HD_)       // 512
#define NREP_ (NH_ / NKV_)       // 4

// ---------------------------------------------------------------------------
// Scratch device globals
// ---------------------------------------------------------------------------
__device__ float g_Qf[(size_t)M_ * QW_];    // fp32 Q pre-rope
__device__ float g_Kf[(size_t)M_ * KVW_];   // fp32 K pre-rope
__device__ bf16 g_Xh[(size_t)M_ * H_],  g_Xl[(size_t)M_ * H_];
__device__ bf16 g_qwh[(size_t)QW_ * H_], g_qwl[(size_t)QW_ * H_];
__device__ bf16 g_kwh[(size_t)KVW_ * H_], g_kwl[(size_t)KVW_ * H_];
__device__ bf16 g_vwh[(size_t)KVW_ * H_], g_vwl[(size_t)KVW_ * H_];
__device__ bf16 g_owh[(size_t)H_ * QW_], g_owl[(size_t)H_ * QW_];
__device__ bf16 g_Qh[(size_t)M_ * QW_],  g_Ql[(size_t)M_ * QW_];
__device__ bf16 g_Kh[(size_t)M_ * KVW_], g_Kl[(size_t)M_ * KVW_];
__device__ bf16 g_Vh[(size_t)M_ * KVW_], g_Vl[(size_t)M_ * KVW_];
__device__ bf16 g_Ah[(size_t)M_ * QW_],  g_Al[(size_t)M_ * QW_];
__device__ float g_cosT[S_ * 64];
__device__ float g_sinT[S_ * 64];

// ---------------------------------------------------------------------------
// Helpers
// ---------------------------------------------------------------------------
__device__ __forceinline__ uint32_t smem_u32(const void* p) {
    return (uint32_t)__cvta_generic_to_shared(p);
}
__device__ __forceinline__ void ldsm_x4(uint32_t* r, uint32_t a) {
    asm volatile("ldmatrix.sync.aligned.m8n8.x4.shared.b16 {%0,%1,%2,%3},[%4];"
        : "=r"(r[0]), "=r"(r[1]), "=r"(r[2]), "=r"(r[3]) : "r"(a));
}
__device__ __forceinline__ void ldsm_x4_t(uint32_t* r, uint32_t a) {
    asm volatile("ldmatrix.sync.aligned.m8n8.x4.trans.shared.b16 {%0,%1,%2,%3},[%4];"
        : "=r"(r[0]), "=r"(r[1]), "=r"(r[2]), "=r"(r[3]) : "r"(a));
}
__device__ __forceinline__ void mma_bf16(float* c, const uint32_t* a, uint32_t b0, uint32_t b1) {
    asm volatile(
        "mma.sync.aligned.m16n8k16.row.col.f32.bf16.bf16.f32 "
        "{%0,%1,%2,%3},{%4,%5,%6,%7},{%8,%9},{%0,%1,%2,%3};"
        : "+f"(c[0]), "+f"(c[1]), "+f"(c[2]), "+f"(c[3])
        : "r"(a[0]), "r"(a[1]), "r"(a[2]), "r"(a[3]), "r"(b0), "r"(b1));
}
__device__ __forceinline__ uint32_t pack2(bf16 a, bf16 b) {
    uint16_t ua = *reinterpret_cast<uint16_t*>(&a);
    uint16_t ub = *reinterpret_cast<uint16_t*>(&b);
    return (uint32_t)ua | ((uint32_t)ub << 16);
}
__device__ __forceinline__ void split2(float x, float y, uint32_t& hi, uint32_t& lo) {
    bf16 hx = __float2bfloat16(x), hy = __float2bfloat16(y);
    float rx = x - __bfloat162float(hx);
    float ry = y - __bfloat162float(hy);
    hi = pack2(hx, hy);
    lo = pack2(__float2bfloat16(rx), __float2bfloat16(ry));
}
__device__ __forceinline__ void cp16(void* dst, const void* src) {
    uint32_t d = smem_u32(dst);
    asm volatile("cp.async.cg.shared.global [%0],[%1],16;" :: "r"(d), "l"(src));
}
__device__ __forceinline__ void cp_commit() {
    asm volatile("cp.async.commit_group;");
}
template <int N> __device__ __forceinline__ void cp_wait() {
    asm volatile("cp.async.wait_group %0;" :: "n"(N));
}

// ---------------------------------------------------------------------------
// Elementwise prep kernels
// ---------------------------------------------------------------------------
__global__ void rope_tables_kernel() {
    int idx = blockIdx.x * blockDim.x + threadIdx.x;
    if (idx >= S_ * 64) return;
    int s = idx >> 6, j = idx & 63;
    double inv_freq = exp(-((double)j / 64.0) * log(10000.0));
    double ang = (double)s * inv_freq;
    g_cosT[idx] = (float)cos(ang);
    g_sinT[idx] = (float)sin(ang);
}

// split fp32 -> bf16 hi/lo, float4 vectorized; n4 = n/4
__global__ void split_kernel(const float* __restrict__ in,
                             bf16* __restrict__ hi, bf16* __restrict__ lo, int n4) {
    int i = blockIdx.x * blockDim.x + threadIdx.x;
    if (i >= n4) return;
    float4 v = ((const float4*)in)[i];
    uint32_t h0, h1, l0, l1;
    split2(v.x, v.y, h0, l0); split2(v.z, v.w, h1, l1);
    ((uint2*)hi)[i] = make_uint2(h0, h1);
    ((uint2*)lo)[i] = make_uint2(l0, l1);
}

// RoPE + split: reads fp32, writes bf16 hi/lo
__global__ void rope_split_kernel(const float* __restrict__ Xf,
                                  bf16* __restrict__ Xh, bf16* __restrict__ Xl,
                                  int nheads, int total) {
    int idx = blockIdx.x * blockDim.x + threadIdx.x;
    if (idx >= total) return;
    int j = idx & 63;
    int t = idx >> 6;
    int h = t % nheads;
    int row = t / nheads;
    int s = row & (S_ - 1);
    float c  = g_cosT[s * 64 + j];
    float sn = g_sinT[s * 64 + j];
    size_t base = (size_t)row * (nheads * HD_) + h * HD_;
    float x1 = Xf[base + j];
    float x2 = Xf[base + j + 64];
    float y1 = x1 * c - x2 * sn;
    float y2 = x2 * c + x1 * sn;
    bf16 h1 = __float2bfloat16(y1);
    bf16 h2 = __float2bfloat16(y2);
    Xh[base + j] = h1;       Xl[base + j]      = __float2bfloat16(y1 - __bfloat162float(h1));
    Xh[base + j + 64] = h2;  Xl[base + j + 64] = __float2bfloat16(y2 - __bfloat162float(h2));
}

// ---------------------------------------------------------------------------
// GEMM (pre-split bf16x3, cp.async 2-stage): C = A @ W^T + bias
// BM=BN=128, BK=64, 256 threads, warp tile 64x32.
// OUT_MODE 0: fp32 C.  OUT_MODE 1: bf16 split (Ch, Cl).
// ---------------------------------------------------------------------------
#define GS 72                      // smem row stride (bf16): 64 + 8 pad
#define GTILE (128 * GS)           // one tile buffer
#define GSTAGE (4 * GTILE)         // Ah,Al,Bh,Bl
#define GEMM_SMEM (2 * GSTAGE * 2) // 2 stages, bytes = 147456

template <int OUT_MODE>
__global__ __launch_bounds__(256, 1)
void gemm_split_tc(const bf16* __restrict__ Agh, const bf16* __restrict__ Agl,
                   const bf16* __restrict__ Bgh, const bf16* __restrict__ Bgl,
                   const float* __restrict__ bias,
                   float* __restrict__ C, bf16* __restrict__ Ch, bf16* __restrict__ Cl,
                   int M, int N, int K) {
    extern __shared__ bf16 smg[];

    const int tid = threadIdx.x;
    const int lane = tid & 31, wid = tid >> 5;
    const int wm = wid >> 2, wn = wid & 3;
    const int bm = blockIdx.y * 128, bn = blockIdx.x * 128;

    const int arow = (lane & 7) + ((lane >> 3) & 1) * 8;
    const int acol = ((lane >> 4) & 1) * 8;
    const int brow = (lane & 7) + ((lane >> 4) & 1) * 8;
    const int bcol = ((lane >> 3) & 1) * 8;

    float acc[4][4][4];
#pragma unroll
    for (int i = 0; i < 4; i++)
#pragma unroll
        for (int j = 0; j < 4; j++)
#pragma unroll
            for (int k = 0; k < 4; k++) acc[i][j][k] = 0.f;

    const int nIter = K / 64;

    auto issue_stage = [&](int t, int buf) {
        const int k0 = t * 64;
        bf16* sb = smg + buf * GSTAGE;
#pragma unroll
        for (int i = 0; i < 16; i++) {
            int id = i * 256 + tid;
            int tile = id >> 10;             // 0:Ah 1:Al 2:Bh 3:Bl
            int rem = id & 1023;
            int r = rem >> 3, ch = rem & 7;
            const bf16* src;
            if (tile == 0)      src = Agh + (size_t)(bm + r) * K + k0 + ch * 8;
            else if (tile == 1) src = Agl + (size_t)(bm + r) * K + k0 + ch * 8;
            else if (tile == 2) src = Bgh + (size_t)(bn + r) * K + k0 + ch * 8;
            else                src = Bgl + (size_t)(bn + r) * K + k0 + ch * 8;
            cp16(sb + tile * GTILE + r * GS + ch * 8, src);
        }
    };

    issue_stage(0, 0);
    cp_commit();

    for (int t = 0; t < nIter; t++) {
        if (t + 1 < nIter) issue_stage(t + 1, (t + 1) & 1);
        cp_commit();
        cp_wait<1>();
        __syncthreads();

        const bf16* pAh = smg + (t & 1) * GSTAGE;
        const bf16* pAl = pAh + GTILE;
        const bf16* pBh = pAl + GTILE;
        const bf16* pBl = pBh + GTILE;

#pragma unroll
        for (int kk = 0; kk < 64; kk += 16) {
            uint32_t fah[4][4], fal[4][4], fbh[2][4], fbl[2][4];
#pragma unroll
            for (int mt = 0; mt < 4; mt++) {
                int r = wm * 64 + mt * 16 + arow;
                ldsm_x4(fah[mt], smem_u32(pAh + r * GS + kk + acol));
                ldsm_x4(fal[mt], smem_u32(pAl + r * GS + kk + acol));
            }
#pragma unroll
            for (int np = 0; np < 2; np++) {
                int r = wn * 32 + np * 16 + brow;
                ldsm_x4(fbh[np], smem_u32(pBh + r * GS + kk + bcol));
                ldsm_x4(fbl[np], smem_u32(pBl + r * GS + kk + bcol));
            }
#pragma unroll
            for (int mt = 0; mt < 4; mt++) {
#pragma unroll
                for (int nt = 0; nt < 4; nt++) {
                    int np = nt >> 1, hf = (nt & 1) * 2;
                    mma_bf16(acc[mt][nt], fah[mt], fbh[np][hf], fbh[np][hf + 1]);
                    mma_bf16(acc[mt][nt], fal[mt], fbh[np][hf], fbh[np][hf + 1]);
                    mma_bf16(acc[mt][nt], fah[mt], fbl[np][hf], fbl[np][hf + 1]);
                }
            }
        }
        __syncthreads();
    }

    // epilogue
    const int g = lane >> 2, c2 = (lane & 3) * 2;
#pragma unroll
    for (int mt = 0; mt < 4; mt++) {
        int row = bm + wm * 64 + mt * 16 + g;
#pragma unroll
        for (int nt = 0; nt < 4; nt++) {
            int col = bn + wn * 32 + nt * 8 + c2;
            float b0 = bias[col], b1 = bias[col + 1];
            float v00 = acc[mt][nt][0] + b0, v01 = acc[mt][nt][1] + b1;
            float v10 = acc[mt][nt][2] + b0, v11 = acc[mt][nt][3] + b1;
            if (OUT_MODE == 0) {
                *(float2*)&C[(size_t)row * N + col]       = make_float2(v00, v01);
                *(float2*)&C[(size_t)(row + 8) * N + col] = make_float2(v10, v11);
            } else {
                uint32_t h0, l0, h1, l1;
                split2(v00, v01, h0, l0);
                split2(v10, v11, h1, l1);
                *(uint32_t*)&Ch[(size_t)row * N + col]       = h0;
                *(uint32_t*)&Cl[(size_t)row * N + col]       = l0;
                *(uint32_t*)&Ch[(size_t)(row + 8) * N + col] = h1;
                *(uint32_t*)&Cl[(size_t)(row + 8) * N + col] = l1;
            }
        }
    }
}

// ---------------------------------------------------------------------------
// Flash attention, register-resident (FA2-style).
// CTA: 128 q-rows x 1 head. 8 warps, each warp owns 16 q-rows, all keys.
// Key tiles of 64, cp.async double-buffered K/V; Q in smem for whole CTA.
// S stays in registers; softmax via shuffles; P repacked in-register to
// A-fragments for the PV mma. bf16x3 throughout.
// ---------------------------------------------------------------------------
#define FQS 136                            // bf16 row stride (128 + 8)
#define FQ_TILE (128 * FQS)                // Q hi or lo
#define FKV_TILE (64 * FQS)                // one K/V hi or lo tile
#define FKV_STAGE (4 * FKV_TILE)           // Kh,Kl,Vh,Vl
#define FA_SMEM ((2 * FQ_TILE + 2 * FKV_STAGE) * 2)  // bytes = 208896

__global__ __launch_bounds__(256, 1)
void flash_reg(const bf16* __restrict__ Qh_g, const bf16* __restrict__ Ql_g,
               const bf16* __restrict__ Kh_g, const bf16* __restrict__ Kl_g,
               const bf16* __restrict__ Vh_g, const bf16* __restrict__ Vl_g,
               bf16* __restrict__ Oh_g, bf16* __restrict__ Ol_g) {
    extern __shared__ bf16 smf[];
    bf16* sQh = smf;
    bf16* sQl = sQh + FQ_TILE;
    bf16* stage0 = sQl + FQ_TILE;

    const int tid = threadIdx.x, lane = tid & 31, wid = tid >> 5;
    const int qt = blockIdx.x, h = blockIdx.y, b = blockIdx.z;
    const int kvh = h / NREP_;
    const float scale = 0.08838834764831845f;

    const int g = lane >> 2;
    const int arow = (lane & 7) + ((lane >> 3) & 1) * 8;
    const int acol = ((lane >> 4) & 1) * 8;
    const int brow = (lane & 7) + ((lane >> 4) & 1) * 8;
    const int bcol = ((lane >> 3) & 1) * 8;
    const int vrow = (lane & 7) + ((lane >> 3) & 1) * 8;
    const int vcol = ((lane >> 4) & 1) * 8;

    // ---- prologue: Q + KV tile 0 (one commit group) ----
    const size_t qb = ((size_t)(b * S_ + qt * 128)) * QW_ + (size_t)h * HD_;
#pragma unroll
    for (int i = 0; i < 16; i++) {
        int id = i * 256 + tid;
        int tile = id >> 11;              // 0: hi, 1: lo
        int rem = id & 2047;
        int r = rem >> 4, ch = rem & 15;
        const bf16* src = (tile ? Ql_g : Qh_g) + qb + (size_t)r * QW_ + ch * 8;
        bf16* dst = (tile ? sQl : sQh) + r * FQS + ch * 8;
        cp16(dst, src);
    }
    auto issue_kv = [&](int kt, int buf) {
        const size_t kb = ((size_t)(b * S_ + kt * 64)) * KVW_ + (size_t)kvh * HD_;
        bf16* sb = stage0 + buf * FKV_STAGE;
#pragma unroll
        for (int i = 0; i < 16; i++) {
            int id = i * 256 + tid;
            int tile = id >> 10;          // 0:Kh 1:Kl 2:Vh 3:Vl
            int rem = id & 1023;
            int r = rem >> 4, ch = rem & 15;
            const bf16* src;
            if (tile == 0)      src = Kh_g + kb + (size_t)r * KVW_ + ch * 8;
            else if (tile == 1) src = Kl_g + kb + (size_t)r * KVW_ + ch * 8;
            else if (tile == 2) src = Vh_g + kb + (size_t)r * KVW_ + ch * 8;
            else                src = Vl_g + kb + (size_t)r * KVW_ + ch * 8;
            cp16(sb + tile * FKV_TILE + r * FQS + ch * 8, src);
        }
    };
    issue_kv(0, 0);
    cp_commit();

    float m_[2] = {-INFINITY, -INFINITY};
    float l_[2] = {0.f, 0.f};
    float oacc[16][4];
#pragma unroll
    for (int i = 0; i < 16; i++)
#pragma unroll
        for (int j = 0; j < 4; j++) oacc[i][j] = 0.f;

    const int NT = S_ / 64;  // 32 key tiles
    for (int kt = 0; kt < NT; kt++) {
        if (kt + 1 < NT) issue_kv(kt + 1, (kt + 1) & 1);
        cp_commit();
        cp_wait<1>();
        __syncthreads();

        const bf16* sKh = stage0 + (kt & 1) * FKV_STAGE;
        const bf16* sKl = sKh + FKV_TILE;
        const bf16* sVh = sKl + FKV_TILE;
        const bf16* sVl = sVh + FKV_TILE;

        // ---- S = Q @ K^T : per warp 16 x 64, K-dim 128 ----
        float sacc[8][4];
#pragma unroll
        for (int i = 0; i < 8; i++)
#pragma unroll
            for (int j = 0; j < 4; j++) sacc[i][j] = 0.f;

#pragma unroll
        for (int kc = 0; kc < 8; kc++) {
            uint32_t qh[4], ql[4], kbh[4][4], kbl[4][4];
            {
                int r = wid * 16 + arow;
                ldsm_x4(qh, smem_u32(sQh + r * FQS + kc * 16 + acol));
                ldsm_x4(ql, smem_u32(sQl + r * FQS + kc * 16 + acol));
            }
#pragma unroll
            for (int ng = 0; ng < 4; ng++) {
                int r = ng * 16 + brow;
                ldsm_x4(kbh[ng], smem_u32(sKh + r * FQS + kc * 16 + bcol));
                ldsm_x4(kbl[ng], smem_u32(sKl + r * FQS + kc * 16 + bcol));
            }
#pragma unroll
            for (int nt = 0; nt < 8; nt++) {
                int np = nt >> 1, hf = (nt & 1) * 2;
                mma_bf16(sacc[nt], qh, kbh[np][hf], kbh[np][hf + 1]);
                mma_bf16(sacc[nt], ql, kbh[np][hf], kbh[np][hf + 1]);
                mma_bf16(sacc[nt], qh, kbl[np][hf], kbl[np][hf + 1]);
            }
        }

        // ---- softmax (registers + shuffles; rows g and g+8) ----
        float mx0 = m_[0], mx1 = m_[1];
#pragma unroll
        for (int nt = 0; nt < 8; nt++) {
            mx0 = fmaxf(mx0, fmaxf(sacc[nt][0], sacc[nt][1]) * scale);
            mx1 = fmaxf(mx1, fmaxf(sacc[nt][2], sacc[nt][3]) * scale);
        }
        mx0 = fmaxf(mx0, __shfl_xor_sync(0xffffffff, mx0, 1));
        mx0 = fmaxf(mx0, __shfl_xor_sync(0xffffffff, mx0, 2));
        mx1 = fmaxf(mx1, __shfl_xor_sync(0xffffffff, mx1, 1));
        mx1 = fmaxf(mx1, __shfl_xor_sync(0xffffffff, mx1, 2));
        float al0 = __expf(m_[0] - mx0);
        float al1 = __expf(m_[1] - mx1);
        m_[0] = mx0; m_[1] = mx1;

        uint32_t pfh[8][2], pfl[8][2];
        float rs0 = 0.f, rs1 = 0.f;
#pragma unroll
        for (int nt = 0; nt < 8; nt++) {
            float p0 = __expf(sacc[nt][0] * scale - mx0);
            float p1 = __expf(sacc[nt][1] * scale - mx0);
            float p2 = __expf(sacc[nt][2] * scale - mx1);
            float p3 = __expf(sacc[nt][3] * scale - mx1);
            rs0 += p0 + p1; rs1 += p2 + p3;
            split2(p0, p1, pfh[nt][0], pfl[nt][0]);
            split2(p2, p3, pfh[nt][1], pfl[nt][1]);
        }
        rs0 += __shfl_xor_sync(0xffffffff, rs0, 1);
        rs0 += __shfl_xor_sync(0xffffffff, rs0, 2);
        rs1 += __shfl_xor_sync(0xffffffff, rs1, 1);
        rs1 += __shfl_xor_sync(0xffffffff, rs1, 2);
        l_[0] = l_[0] * al0 + rs0;
        l_[1] = l_[1] * al1 + rs1;

#pragma unroll
        for (int nt = 0; nt < 16; nt++) {
            oacc[nt][0] *= al0; oacc[nt][1] *= al0;
            oacc[nt][2] *= al1; oacc[nt][3] *= al1;
        }

        // ---- O += P @ V : per warp 16 x 128, K-dim 64 keys ----
#pragma unroll
        for (int kc = 0; kc < 4; kc++) {
            uint32_t ah[4] = {pfh[2 * kc][0], pfh[2 * kc][1], pfh[2 * kc + 1][0], pfh[2 * kc + 1][1]};
            uint32_t alr[4] = {pfl[2 * kc][0], pfl[2 * kc][1], pfl[2 * kc + 1][0], pfl[2 * kc + 1][1]};
#pragma unroll
            for (int dh = 0; dh < 2; dh++) {
                uint32_t vbh[4][4], vbl[4][4];
#pragma unroll
                for (int ng = 0; ng < 4; ng++) {
                    int cbase = dh * 64 + ng * 16;
                    ldsm_x4_t(vbh[ng], smem_u32(sVh + (kc * 16 + vrow) * FQS + cbase + vcol));
                    ldsm_x4_t(vbl[ng], smem_u32(sVl + (kc * 16 + vrow) * FQS + cbase + vcol));
                }
#pragma unroll
                for (int nt = 0; nt < 8; nt++) {
                    int np = nt >> 1, hf = (nt & 1) * 2;
                    float* oc = oacc[dh * 8 + nt];
                    mma_bf16(oc, ah, vbh[np][hf], vbh[np][hf + 1]);
                    mma_bf16(oc, alr, vbh[np][hf], vbh[np][hf + 1]);
                    mma_bf16(oc, ah, vbl[np][hf], vbl[np][hf + 1]);
                }
            }
        }
        __syncthreads();
    }

    // ---- epilogue: normalize, split, store ----
    float inv0 = 1.f / (l_[0] + 1e-10f);
    float inv1 = 1.f / (l_[1] + 1e-10f);
    const int c2 = (lane & 3) * 2;
    const size_t ob = ((size_t)(b * S_ + qt * 128 + wid * 16 + g)) * QW_ + (size_t)h * HD_;
#pragma unroll
    for (int nt = 0; nt < 16; nt++) {
        int col = nt * 8 + c2;
        uint32_t h0, l0, h1, l1;
        split2(oacc[nt][0] * inv0, oacc[nt][1] * inv0, h0, l0);
        split2(oacc[nt][2] * inv1, oacc[nt][3] * inv1, h1, l1);
        *(uint32_t*)&Oh_g[ob + col] = h0;
        *(uint32_t*)&Ol_g[ob + col] = l0;
        *(uint32_t*)&Oh_g[ob + 8 * QW_ + col] = h1;
        *(uint32_t*)&Ol_g[ob + 8 * QW_ + col] = l1;
    }
}

// ---------------------------------------------------------------------------
// Launch
// ---------------------------------------------------------------------------
extern "C" void kernel_launch(void* const* d_in, const int* in_sizes, int n_in,
                              void* d_out, int out_size) {
    const float* X   = (const float*)d_in[0];
    const float* q_w = (const float*)d_in[1];
    const float* q_b = (const float*)d_in[2];
    const float* k_w = (const float*)d_in[3];
    const float* k_b = (const float*)d_in[4];
    const float* v_w = (const float*)d_in[5];
    const float* v_b = (const float*)d_in[6];
    const float* o_w = (const float*)d_in[7];
    const float* o_b = (const float*)d_in[8];
    float* out = (float*)d_out;

    float *pQf, *pKf;
    bf16 *pXh, *pXl, *pqwh, *pqwl, *pkwh, *pkwl, *pvwh, *pvwl, *powh, *powl;
    bf16 *pQh, *pQl, *pKh, *pKl, *pVh, *pVl, *pAh, *pAl;
    cudaGetSymbolAddress((void**)&pQf, g_Qf);
    cudaGetSymbolAddress((void**)&pKf, g_Kf);
    cudaGetSymbolAddress((void**)&pXh, g_Xh);   cudaGetSymbolAddress((void**)&pXl, g_Xl);
    cudaGetSymbolAddress((void**)&pqwh, g_qwh); cudaGetSymbolAddress((void**)&pqwl, g_qwl);
    cudaGetSymbolAddress((void**)&pkwh, g_kwh); cudaGetSymbolAddress((void**)&pkwl, g_kwl);
    cudaGetSymbolAddress((void**)&pvwh, g_vwh); cudaGetSymbolAddress((void**)&pvwl, g_vwl);
    cudaGetSymbolAddress((void**)&powh, g_owh); cudaGetSymbolAddress((void**)&powl, g_owl);
    cudaGetSymbolAddress((void**)&pQh, g_Qh);   cudaGetSymbolAddress((void**)&pQl, g_Ql);
    cudaGetSymbolAddress((void**)&pKh, g_Kh);   cudaGetSymbolAddress((void**)&pKl, g_Kl);
    cudaGetSymbolAddress((void**)&pVh, g_Vh);   cudaGetSymbolAddress((void**)&pVl, g_Vl);
    cudaGetSymbolAddress((void**)&pAh, g_Ah);   cudaGetSymbolAddress((void**)&pAl, g_Al);

    cudaFuncSetAttribute(gemm_split_tc<0>, cudaFuncAttributeMaxDynamicSharedMemorySize, GEMM_SMEM);
    cudaFuncSetAttribute(gemm_split_tc<1>, cudaFuncAttributeMaxDynamicSharedMemorySize, GEMM_SMEM);
    cudaFuncSetAttribute(flash_reg, cudaFuncAttributeMaxDynamicSharedMemorySize, FA_SMEM);

    // Tables + splits
    rope_tables_kernel<<<(S_ * 64 + 255) / 256, 256>>>();
    split_kernel<<<((M_ * H_ / 4) + 255) / 256, 256>>>(X, pXh, pXl, M_ * H_ / 4);
    split_kernel<<<((QW_ * H_ / 4) + 255) / 256, 256>>>(q_w, pqwh, pqwl, QW_ * H_ / 4);
    split_kernel<<<((KVW_ * H_ / 4) + 255) / 256, 256>>>(k_w, pkwh, pkwl, KVW_ * H_ / 4);
    split_kernel<<<((KVW_ * H_ / 4) + 255) / 256, 256>>>(v_w, pvwh, pvwl, KVW_ * H_ / 4);
    split_kernel<<<((H_ * QW_ / 4) + 255) / 256, 256>>>(o_w, powh, powl, H_ * QW_ / 4);

    // Projections (Q,K -> fp32 for RoPE; V -> split bf16 directly)
    gemm_split_tc<0><<<dim3(QW_ / 128, M_ / 128), 256, GEMM_SMEM>>>(
        pXh, pXl, pqwh, pqwl, q_b, pQf, nullptr, nullptr, M_, QW_, H_);
    gemm_split_tc<0><<<dim3(KVW_ / 128, M_ / 128), 256, GEMM_SMEM>>>(
        pXh, pXl, pkwh, pkwl, k_b, pKf, nullptr, nullptr, M_, KVW_, H_);
    gemm_split_tc<1><<<dim3(KVW_ / 128, M_ / 128), 256, GEMM_SMEM>>>(
        pXh, pXl, pvwh, pvwl, v_b, nullptr, pVh, pVl, M_, KVW_, H_);

    // RoPE + split
    rope_split_kernel<<<(M_ * NH_ * 64 + 255) / 256, 256>>>(pQf, pQh, pQl, NH_, M_ * NH_ * 64);
    rope_split_kernel<<<(M_ * NKV_ * 64 + 255) / 256, 256>>>(pKf, pKh, pKl, NKV_, M_ * NKV_ * 64);

    // Attention (writes split bf16 A)
    flash_reg<<<dim3(S_ / 128, NH_, B_), 256, FA_SMEM>>>(
        pQh, pQl, pKh, pKl, pVh, pVl, pAh, pAl);

    // Output projection
    gemm_split_tc<0><<<dim3(H_ / 128, M_ / 128), 256, GEMM_SMEM>>>(
        pAh, pAl, powh, powl, o_b, out, nullptr, nullptr, M_, H_, H_);
}

// round 5
// speedup vs baseline: 4.6531x; 1.2474x over previous
#include <cuda_runtime.h>
#include <cuda_bf16.h>
#include <cuda_fp16.h>
#include <math.h>
#include <stdint.h>

typedef __nv_bfloat16 bf16;
typedef __half fp16;

// Problem constants
#define B_    2
#define S_    2048
#define H_    2048
#define NH_   16
#define NKV_  4
#define HD_   128
#define M_    (B_ * S_)          // 4096
#define QW_   (NH_ * HD_)        // 2048
#define KVW_  (NKV_ * HD_)       // 512
#define NREP_ (NH_ / NKV_)       // 4
#define QKVW_ 3072               // merged Q|K|V width

// ---------------------------------------------------------------------------
// Scratch device globals
// ---------------------------------------------------------------------------
__device__ float g_QKVf[(size_t)M_ * QKVW_];   // fused projection out (fp32)
__device__ float g_qkvb[QKVW_];
__device__ bf16 g_Xh[(size_t)M_ * H_],  g_Xl[(size_t)M_ * H_];
__device__ bf16 g_wh[(size_t)QKVW_ * H_], g_wl[(size_t)QKVW_ * H_];   // merged qkv weights
__device__ bf16 g_owh[(size_t)H_ * QW_], g_owl[(size_t)H_ * QW_];
__device__ fp16 g_Qh[(size_t)M_ * QW_],  g_Ql[(size_t)M_ * QW_];       // fp16 hi/lo Q (roped)
__device__ fp16 g_K16[(size_t)M_ * KVW_];                              // fp16 K (roped)
__device__ fp16 g_V16[(size_t)M_ * KVW_];                              // fp16 V
__device__ bf16 g_Ah[(size_t)M_ * QW_],  g_Al[(size_t)M_ * QW_];       // attention out (split)
__device__ float g_cosT[S_ * 64];
__device__ float g_sinT[S_ * 64];

// ---------------------------------------------------------------------------
// Helpers
// ---------------------------------------------------------------------------
__device__ __forceinline__ uint32_t smem_u32(const void* p) {
    return (uint32_t)__cvta_generic_to_shared(p);
}
__device__ __forceinline__ void ldsm_x4(uint32_t* r, uint32_t a) {
    asm volatile("ldmatrix.sync.aligned.m8n8.x4.shared.b16 {%0,%1,%2,%3},[%4];"
        : "=r"(r[0]), "=r"(r[1]), "=r"(r[2]), "=r"(r[3]) : "r"(a));
}
__device__ __forceinline__ void ldsm_x4_t(uint32_t* r, uint32_t a) {
    asm volatile("ldmatrix.sync.aligned.m8n8.x4.trans.shared.b16 {%0,%1,%2,%3},[%4];"
        : "=r"(r[0]), "=r"(r[1]), "=r"(r[2]), "=r"(r[3]) : "r"(a));
}
__device__ __forceinline__ void mma_bf16(float* c, const uint32_t* a, uint32_t b0, uint32_t b1) {
    asm volatile(
        "mma.sync.aligned.m16n8k16.row.col.f32.bf16.bf16.f32 "
        "{%0,%1,%2,%3},{%4,%5,%6,%7},{%8,%9},{%0,%1,%2,%3};"
        : "+f"(c[0]), "+f"(c[1]), "+f"(c[2]), "+f"(c[3])
        : "r"(a[0]), "r"(a[1]), "r"(a[2]), "r"(a[3]), "r"(b0), "r"(b1));
}
__device__ __forceinline__ void mma_f16(float* c, const uint32_t* a, uint32_t b0, uint32_t b1) {
    asm volatile(
        "mma.sync.aligned.m16n8k16.row.col.f32.f16.f16.f32 "
        "{%0,%1,%2,%3},{%4,%5,%6,%7},{%8,%9},{%0,%1,%2,%3};"
        : "+f"(c[0]), "+f"(c[1]), "+f"(c[2]), "+f"(c[3])
        : "r"(a[0]), "r"(a[1]), "r"(a[2]), "r"(a[3]), "r"(b0), "r"(b1));
}
__device__ __forceinline__ uint32_t pack2(bf16 a, bf16 b) {
    uint16_t ua = *reinterpret_cast<uint16_t*>(&a);
    uint16_t ub = *reinterpret_cast<uint16_t*>(&b);
    return (uint32_t)ua | ((uint32_t)ub << 16);
}
__device__ __forceinline__ void split2(float x, float y, uint32_t& hi, uint32_t& lo) {
    bf16 hx = __float2bfloat16(x), hy = __float2bfloat16(y);
    float rx = x - __bfloat162float(hx);
    float ry = y - __bfloat162float(hy);
    hi = pack2(hx, hy);
    lo = pack2(__float2bfloat16(rx), __float2bfloat16(ry));
}
__device__ __forceinline__ uint32_t packh2(float a, float b) {
    __half2 h = __floats2half2_rn(a, b);
    return *reinterpret_cast<uint32_t*>(&h);
}
__device__ __forceinline__ void cp16(void* dst, const void* src) {
    uint32_t d = smem_u32(dst);
    asm volatile("cp.async.cg.shared.global [%0],[%1],16;" :: "r"(d), "l"(src));
}
__device__ __forceinline__ void cp_commit() {
    asm volatile("cp.async.commit_group;");
}
template <int N> __device__ __forceinline__ void cp_wait() {
    asm volatile("cp.async.wait_group %0;" :: "n"(N));
}

// ---------------------------------------------------------------------------
// Elementwise prep kernels
// ---------------------------------------------------------------------------
__global__ void rope_tables_kernel() {
    int idx = blockIdx.x * blockDim.x + threadIdx.x;
    if (idx >= S_ * 64) return;
    int s = idx >> 6, j = idx & 63;
    double inv_freq = exp(-((double)j / 64.0) * log(10000.0));
    double ang = (double)s * inv_freq;
    g_cosT[idx] = (float)cos(ang);
    g_sinT[idx] = (float)sin(ang);
}

__global__ void split_kernel(const float* __restrict__ in,
                             bf16* __restrict__ hi, bf16* __restrict__ lo, int n4) {
    int i = blockIdx.x * blockDim.x + threadIdx.x;
    if (i >= n4) return;
    float4 v = ((const float4*)in)[i];
    uint32_t h0, h1, l0, l1;
    split2(v.x, v.y, h0, l0); split2(v.z, v.w, h1, l1);
    ((uint2*)hi)[i] = make_uint2(h0, h1);
    ((uint2*)lo)[i] = make_uint2(l0, l1);
}

__global__ void concat_bias_kernel(const float* __restrict__ qb,
                                   const float* __restrict__ kb,
                                   const float* __restrict__ vb) {
    int i = threadIdx.x + blockIdx.x * blockDim.x;
    if (i < 2048) g_qkvb[i] = qb[i];
    else if (i < 2560) g_qkvb[i] = kb[i - 2048];
    else if (i < 3072) g_qkvb[i] = vb[i - 2560];
}

// RoPE Q: read fused buffer cols [0,2048), emit fp16 hi/lo
__global__ void rope_q_fp16(const float* __restrict__ QKVf,
                            fp16* __restrict__ Qh, fp16* __restrict__ Ql, int total) {
    int idx = blockIdx.x * blockDim.x + threadIdx.x;
    if (idx >= total) return;
    int j = idx & 63;
    int t = idx >> 6;
    int h = t % NH_;
    int row = t / NH_;
    int s = row & (S_ - 1);
    float c  = g_cosT[s * 64 + j];
    float sn = g_sinT[s * 64 + j];
    size_t ib = (size_t)row * QKVW_ + h * HD_;
    size_t ob = (size_t)row * QW_ + h * HD_;
    float x1 = QKVf[ib + j];
    float x2 = QKVf[ib + j + 64];
    float y1 = x1 * c - x2 * sn;
    float y2 = x2 * c + x1 * sn;
    fp16 h1 = __float2half_rn(y1);
    fp16 h2 = __float2half_rn(y2);
    Qh[ob + j]      = h1;  Ql[ob + j]      = __float2half_rn(y1 - __half2float(h1));
    Qh[ob + j + 64] = h2;  Ql[ob + j + 64] = __float2half_rn(y2 - __half2float(h2));
}

// RoPE K: read fused cols [2048,2560), emit single fp16
__global__ void rope_k_fp16(const float* __restrict__ QKVf, fp16* __restrict__ K16, int total) {
    int idx = blockIdx.x * blockDim.x + threadIdx.x;
    if (idx >= total) return;
    int j = idx & 63;
    int t = idx >> 6;
    int h = t % NKV_;
    int row = t / NKV_;
    int s = row & (S_ - 1);
    float c  = g_cosT[s * 64 + j];
    float sn = g_sinT[s * 64 + j];
    size_t ib = (size_t)row * QKVW_ + 2048 + h * HD_;
    size_t ob = (size_t)row * KVW_ + h * HD_;
    float x1 = QKVf[ib + j];
    float x2 = QKVf[ib + j + 64];
    K16[ob + j]      = __float2half_rn(x1 * c - x2 * sn);
    K16[ob + j + 64] = __float2half_rn(x2 * c + x1 * sn);
}

// V: fused cols [2560,3072) fp32 -> fp16
__global__ void vhalf_kernel(const float* __restrict__ QKVf, fp16* __restrict__ V16, int n4) {
    int i = blockIdx.x * blockDim.x + threadIdx.x;
    if (i >= n4) return;                  // n4 = M_*512/4
    int row = i >> 7;
    int c4 = (i & 127) * 4;
    float4 v = *(const float4*)&QKVf[(size_t)row * QKVW_ + 2560 + c4];
    uint2 o;
    o.x = packh2(v.x, v.y);
    o.y = packh2(v.z, v.w);
    *(uint2*)&V16[(size_t)row * KVW_ + c4] = o;
}

// ---------------------------------------------------------------------------
// GEMM (pre-split bf16x3, cp.async 3-stage): C = A @ W^T + bias (fp32 out)
// BM=BN=128, BK=64, 256 threads, warp tile 64x32.
// ---------------------------------------------------------------------------
#define GS 72                      // smem row stride (bf16): 64 + 8 pad
#define GTILE (128 * GS)
#define GSTAGE (4 * GTILE)         // Ah,Al,Bh,Bl
#define GEMM_SMEM (3 * GSTAGE * 2) // 3 stages = 221184 B

__global__ __launch_bounds__(256, 1)
void gemm_tc3(const bf16* __restrict__ Agh, const bf16* __restrict__ Agl,
              const bf16* __restrict__ Bgh, const bf16* __restrict__ Bgl,
              const float* __restrict__ bias, float* __restrict__ C,
              int M, int N, int K) {
    extern __shared__ bf16 smg[];

    const int tid = threadIdx.x;
    const int lane = tid & 31, wid = tid >> 5;
    const int wm = wid >> 2, wn = wid & 3;
    const int bm = blockIdx.y * 128, bn = blockIdx.x * 128;

    const int arow = (lane & 7) + ((lane >> 3) & 1) * 8;
    const int acol = ((lane >> 4) & 1) * 8;
    const int brow = (lane & 7) + ((lane >> 4) & 1) * 8;
    const int bcol = ((lane >> 3) & 1) * 8;

    float acc[4][4][4];
#pragma unroll
    for (int i = 0; i < 4; i++)
#pragma unroll
        for (int j = 0; j < 4; j++)
#pragma unroll
            for (int k = 0; k < 4; k++) acc[i][j][k] = 0.f;

    const int nIter = K / 64;

    auto issue_stage = [&](int t) {
        if (t < nIter) {
            const int k0 = t * 64;
            bf16* sb = smg + (t % 3) * GSTAGE;
#pragma unroll
            for (int i = 0; i < 16; i++) {
                int id = i * 256 + tid;
                int tile = id >> 10;
                int rem = id & 1023;
                int r = rem >> 3, ch = rem & 7;
                const bf16* src;
                if (tile == 0)      src = Agh + (size_t)(bm + r) * K + k0 + ch * 8;
                else if (tile == 1) src = Agl + (size_t)(bm + r) * K + k0 + ch * 8;
                else if (tile == 2) src = Bgh + (size_t)(bn + r) * K + k0 + ch * 8;
                else                src = Bgl + (size_t)(bn + r) * K + k0 + ch * 8;
                cp16(sb + tile * GTILE + r * GS + ch * 8, src);
            }
        }
        cp_commit();
    };

    issue_stage(0);
    issue_stage(1);

    for (int t = 0; t < nIter; t++) {
        cp_wait<1>();
        __syncthreads();
        issue_stage(t + 2);

        const bf16* pAh = smg + (t % 3) * GSTAGE;
        const bf16* pAl = pAh + GTILE;
        const bf16* pBh = pAl + GTILE;
        const bf16* pBl = pBh + GTILE;

#pragma unroll
        for (int kk = 0; kk < 64; kk += 16) {
            uint32_t fah[4][4], fal[4][4], fbh[2][4], fbl[2][4];
#pragma unroll
            for (int mt = 0; mt < 4; mt++) {
                int r = wm * 64 + mt * 16 + arow;
                ldsm_x4(fah[mt], smem_u32(pAh + r * GS + kk + acol));
                ldsm_x4(fal[mt], smem_u32(pAl + r * GS + kk + acol));
            }
#pragma unroll
            for (int np = 0; np < 2; np++) {
                int r = wn * 32 + np * 16 + brow;
                ldsm_x4(fbh[np], smem_u32(pBh + r * GS + kk + bcol));
                ldsm_x4(fbl[np], smem_u32(pBl + r * GS + kk + bcol));
            }
#pragma unroll
            for (int mt = 0; mt < 4; mt++) {
#pragma unroll
                for (int nt = 0; nt < 4; nt++) {
                    int np = nt >> 1, hf = (nt & 1) * 2;
                    mma_bf16(acc[mt][nt], fah[mt], fbh[np][hf], fbh[np][hf + 1]);
                    mma_bf16(acc[mt][nt], fal[mt], fbh[np][hf], fbh[np][hf + 1]);
                    mma_bf16(acc[mt][nt], fah[mt], fbl[np][hf], fbl[np][hf + 1]);
                }
            }
        }
    }

    const int g = lane >> 2, c2 = (lane & 3) * 2;
#pragma unroll
    for (int mt = 0; mt < 4; mt++) {
        int row = bm + wm * 64 + mt * 16 + g;
#pragma unroll
        for (int nt = 0; nt < 4; nt++) {
            int col = bn + wn * 32 + nt * 8 + c2;
            float b0 = bias[col], b1 = bias[col + 1];
            *(float2*)&C[(size_t)row * N + col] =
                make_float2(acc[mt][nt][0] + b0, acc[mt][nt][1] + b1);
            *(float2*)&C[(size_t)(row + 8) * N + col] =
                make_float2(acc[mt][nt][2] + b0, acc[mt][nt][3] + b1);
        }
    }
}

// ---------------------------------------------------------------------------
// Flash attention, fp16 operands.
// CTA: 128 q-rows x 1 head, 8 warps x 16 rows. Q fragments held in registers.
// K single fp16 (S = Qh*K + Ql*K, 2 mma), V single fp16 (PV = P_fp16*V, 1 mma).
// 3-stage cp.async KV pipeline. Output: bf16 hi/lo split (feeds O-proj).
// ---------------------------------------------------------------------------
#define FQS 136                            // fp16 row stride (128 + 8)
#define FQ_TILE (128 * FQS)                // Q hi or lo (halves)
#define FKV_TILE (64 * FQS)                // one K or V tile (halves)
#define FKV_STAGE (2 * FKV_TILE)           // K + V
#define FA_SMEM ((2 * FQ_TILE + 3 * FKV_STAGE) * 2)   // 174080 B

__global__ __launch_bounds__(256, 1)
void flash_fp16(const fp16* __restrict__ Qh_g, const fp16* __restrict__ Ql_g,
                const fp16* __restrict__ K_g, const fp16* __restrict__ V_g,
                bf16* __restrict__ Oh_g, bf16* __restrict__ Ol_g) {
    extern __shared__ fp16 smf[];
    fp16* sQh = smf;
    fp16* sQl = sQh + FQ_TILE;
    fp16* stage0 = sQl + FQ_TILE;

    const int tid = threadIdx.x, lane = tid & 31, wid = tid >> 5;
    const int qt = blockIdx.x, h = blockIdx.y, b = blockIdx.z;
    const int kvh = h / NREP_;
    const float scale = 0.08838834764831845f;

    const int g = lane >> 2;
    const int arow = (lane & 7) + ((lane >> 3) & 1) * 8;
    const int acol = ((lane >> 4) & 1) * 8;
    const int brow = (lane & 7) + ((lane >> 4) & 1) * 8;
    const int bcol = ((lane >> 3) & 1) * 8;
    const int vrow = (lane & 7) + ((lane >> 3) & 1) * 8;
    const int vcol = ((lane >> 4) & 1) * 8;

    // ---- prologue: Q (own group), then KV stages 0,1 ----
    const size_t qb = ((size_t)(b * S_ + qt * 128)) * QW_ + (size_t)h * HD_;
#pragma unroll
    for (int i = 0; i < 16; i++) {
        int id = i * 256 + tid;
        int tile = id >> 11;              // 0: hi, 1: lo
        int rem = id & 2047;
        int r = rem >> 4, ch = rem & 15;
        const fp16* src = (tile ? Ql_g : Qh_g) + qb + (size_t)r * QW_ + ch * 8;
        fp16* dst = (tile ? sQl : sQh) + r * FQS + ch * 8;
        cp16(dst, src);
    }
    cp_commit();

    auto issue_kv = [&](int kt) {
        if (kt < S_ / 64) {
            const size_t kb = ((size_t)(b * S_ + kt * 64)) * KVW_ + (size_t)kvh * HD_;
            fp16* sb = stage0 + (kt % 3) * FKV_STAGE;
#pragma unroll
            for (int i = 0; i < 8; i++) {
                int id = i * 256 + tid;
                int tile = id >> 10;       // 0:K 1:V
                int rem = id & 1023;
                int r = rem >> 4, ch = rem & 15;
                const fp16* src = (tile ? V_g : K_g) + kb + (size_t)r * KVW_ + ch * 8;
                cp16(sb + tile * FKV_TILE + r * FQS + ch * 8, src);
            }
        }
        cp_commit();
    };
    issue_kv(0);
    issue_kv(1);

    // ---- Q fragment preload into registers ----
    cp_wait<2>();          // Q group retired
    __syncthreads();
    uint32_t qfh[8][4], qfl[8][4];
#pragma unroll
    for (int kc = 0; kc < 8; kc++) {
        int r = wid * 16 + arow;
        ldsm_x4(qfh[kc], smem_u32(sQh + r * FQS + kc * 16 + acol));
        ldsm_x4(qfl[kc], smem_u32(sQl + r * FQS + kc * 16 + acol));
    }

    float m_[2] = {-INFINITY, -INFINITY};
    float l_[2] = {0.f, 0.f};
    float oacc[16][4];
#pragma unroll
    for (int i = 0; i < 16; i++)
#pragma unroll
        for (int j = 0; j < 4; j++) oacc[i][j] = 0.f;

    const int NT = S_ / 64;
    for (int kt = 0; kt < NT; kt++) {
        cp_wait<1>();
        __syncthreads();
        issue_kv(kt + 2);

        const fp16* sK = stage0 + (kt % 3) * FKV_STAGE;
        const fp16* sV = sK + FKV_TILE;

        // ---- S = Q @ K^T (fp16 x2) ----
        float sacc[8][4];
#pragma unroll
        for (int i = 0; i < 8; i++)
#pragma unroll
            for (int j = 0; j < 4; j++) sacc[i][j] = 0.f;

#pragma unroll
        for (int kc = 0; kc < 8; kc++) {
            uint32_t kb_[4][4];
#pragma unroll
            for (int ng = 0; ng < 4; ng++) {
                int r = ng * 16 + brow;
                ldsm_x4(kb_[ng], smem_u32(sK + r * FQS + kc * 16 + bcol));
            }
#pragma unroll
            for (int nt = 0; nt < 8; nt++) {
                int np = nt >> 1, hf = (nt & 1) * 2;
                mma_f16(sacc[nt], qfh[kc], kb_[np][hf], kb_[np][hf + 1]);
                mma_f16(sacc[nt], qfl[kc], kb_[np][hf], kb_[np][hf + 1]);
            }
        }

        // ---- online softmax (registers + shuffles) ----
        float mx0 = m_[0], mx1 = m_[1];
#pragma unroll
        for (int nt = 0; nt < 8; nt++) {
            mx0 = fmaxf(mx0, fmaxf(sacc[nt][0], sacc[nt][1]) * scale);
            mx1 = fmaxf(mx1, fmaxf(sacc[nt][2], sacc[nt][3]) * scale);
        }
        mx0 = fmaxf(mx0, __shfl_xor_sync(0xffffffff, mx0, 1));
        mx0 = fmaxf(mx0, __shfl_xor_sync(0xffffffff, mx0, 2));
        mx1 = fmaxf(mx1, __shfl_xor_sync(0xffffffff, mx1, 1));
        mx1 = fmaxf(mx1, __shfl_xor_sync(0xffffffff, mx1, 2));
        float al0 = __expf(m_[0] - mx0);
        float al1 = __expf(m_[1] - mx1);
        m_[0] = mx0; m_[1] = mx1;

        uint32_t pf[8][2];
        float rs0 = 0.f, rs1 = 0.f;
#pragma unroll
        for (int nt = 0; nt < 8; nt++) {
            float p0 = __expf(sacc[nt][0] * scale - mx0);
            float p1 = __expf(sacc[nt][1] * scale - mx0);
            float p2 = __expf(sacc[nt][2] * scale - mx1);
            float p3 = __expf(sacc[nt][3] * scale - mx1);
            rs0 += p0 + p1; rs1 += p2 + p3;
            pf[nt][0] = packh2(p0, p1);
            pf[nt][1] = packh2(p2, p3);
        }
        rs0 += __shfl_xor_sync(0xffffffff, rs0, 1);
        rs0 += __shfl_xor_sync(0xffffffff, rs0, 2);
        rs1 += __shfl_xor_sync(0xffffffff, rs1, 1);
        rs1 += __shfl_xor_sync(0xffffffff, rs1, 2);
        l_[0] = l_[0] * al0 + rs0;
        l_[1] = l_[1] * al1 + rs1;

#pragma unroll
        for (int nt = 0; nt < 16; nt++) {
            oacc[nt][0] *= al0; oacc[nt][1] *= al0;
            oacc[nt][2] *= al1; oacc[nt][3] *= al1;
        }

        // ---- O += P(fp16) @ V(fp16) ----
#pragma unroll
        for (int kc = 0; kc < 4; kc++) {
            uint32_t ah[4] = {pf[2 * kc][0], pf[2 * kc][1], pf[2 * kc + 1][0], pf[2 * kc + 1][1]};
#pragma unroll
            for (int dh = 0; dh < 2; dh++) {
                uint32_t vb_[4][4];
#pragma unroll
                for (int ng = 0; ng < 4; ng++) {
                    int cbase = dh * 64 + ng * 16;
                    ldsm_x4_t(vb_[ng], smem_u32(sV + (kc * 16 + vrow) * FQS + cbase + vcol));
                }
#pragma unroll
                for (int nt = 0; nt < 8; nt++) {
                    int np = nt >> 1, hf = (nt & 1) * 2;
                    mma_f16(oacc[dh * 8 + nt], ah, vb_[np][hf], vb_[np][hf + 1]);
                }
            }
        }
    }

    // ---- epilogue: normalize, split to bf16 hi/lo, store ----
    float inv0 = 1.f / (l_[0] + 1e-10f);
    float inv1 = 1.f / (l_[1] + 1e-10f);
    const int c2 = (lane & 3) * 2;
    const size_t ob = ((size_t)(b * S_ + qt * 128 + wid * 16 + g)) * QW_ + (size_t)h * HD_;
#pragma unroll
    for (int nt = 0; nt < 16; nt++) {
        int col = nt * 8 + c2;
        uint32_t h0, l0, h1, l1;
        split2(oacc[nt][0] * inv0, oacc[nt][1] * inv0, h0, l0);
        split2(oacc[nt][2] * inv1, oacc[nt][3] * inv1, h1, l1);
        *(uint32_t*)&Oh_g[ob + col] = h0;
        *(uint32_t*)&Ol_g[ob + col] = l0;
        *(uint32_t*)&Oh_g[ob + 8 * QW_ + col] = h1;
        *(uint32_t*)&Ol_g[ob + 8 * QW_ + col] = l1;
    }
}

// ---------------------------------------------------------------------------
// Launch
// ---------------------------------------------------------------------------
extern "C" void kernel_launch(void* const* d_in, const int* in_sizes, int n_in,
                              void* d_out, int out_size) {
    const float* X   = (const float*)d_in[0];
    const float* q_w = (const float*)d_in[1];
    const float* q_b = (const float*)d_in[2];
    const float* k_w = (const float*)d_in[3];
    const float* k_b = (const float*)d_in[4];
    const float* v_w = (const float*)d_in[5];
    const float* v_b = (const float*)d_in[6];
    const float* o_w = (const float*)d_in[7];
    const float* o_b = (const float*)d_in[8];
    float* out = (float*)d_out;

    float *pQKVf, *pqkvb;
    bf16 *pXh, *pXl, *pwh, *pwl, *powh, *powl, *pAh, *pAl;
    fp16 *pQh, *pQl, *pK16, *pV16;
    cudaGetSymbolAddress((void**)&pQKVf, g_QKVf);
    cudaGetSymbolAddress((void**)&pqkvb, g_qkvb);
    cudaGetSymbolAddress((void**)&pXh, g_Xh);   cudaGetSymbolAddress((void**)&pXl, g_Xl);
    cudaGetSymbolAddress((void**)&pwh, g_wh);   cudaGetSymbolAddress((void**)&pwl, g_wl);
    cudaGetSymbolAddress((void**)&powh, g_owh); cudaGetSymbolAddress((void**)&powl, g_owl);
    cudaGetSymbolAddress((void**)&pAh, g_Ah);   cudaGetSymbolAddress((void**)&pAl, g_Al);
    cudaGetSymbolAddress((void**)&pQh, g_Qh);   cudaGetSymbolAddress((void**)&pQl, g_Ql);
    cudaGetSymbolAddress((void**)&pK16, g_K16); cudaGetSymbolAddress((void**)&pV16, g_V16);

    cudaFuncSetAttribute(gemm_tc3, cudaFuncAttributeMaxDynamicSharedMemorySize, GEMM_SMEM);
    cudaFuncSetAttribute(flash_fp16, cudaFuncAttributeMaxDynamicSharedMemorySize, FA_SMEM);

    // Tables + input/weight splits
    rope_tables_kernel<<<(S_ * 64 + 255) / 256, 256>>>();
    split_kernel<<<((M_ * H_ / 4) + 255) / 256, 256>>>(X, pXh, pXl, M_ * H_ / 4);
    split_kernel<<<((QW_ * H_ / 4) + 255) / 256, 256>>>(q_w, pwh, pwl, QW_ * H_ / 4);
    split_kernel<<<((KVW_ * H_ / 4) + 255) / 256, 256>>>(
        k_w, pwh + (size_t)2048 * H_, pwl + (size_t)2048 * H_, KVW_ * H_ / 4);
    split_kernel<<<((KVW_ * H_ / 4) + 255) / 256, 256>>>(
        v_w, pwh + (size_t)2560 * H_, pwl + (size_t)2560 * H_, KVW_ * H_ / 4);
    split_kernel<<<((H_ * QW_ / 4) + 255) / 256, 256>>>(o_w, powh, powl, H_ * QW_ / 4);
    concat_bias_kernel<<<12, 256>>>(q_b, k_b, v_b);

    // Fused QKV projection (768 CTAs)
    gemm_tc3<<<dim3(QKVW_ / 128, M_ / 128), 256, GEMM_SMEM>>>(
        pXh, pXl, pwh, pwl, pqkvb, pQKVf, M_, QKVW_, H_);

    // RoPE + fp16 conversion
    rope_q_fp16<<<(M_ * NH_ * 64 + 255) / 256, 256>>>(pQKVf, pQh, pQl, M_ * NH_ * 64);
    rope_k_fp16<<<(M_ * NKV_ * 64 + 255) / 256, 256>>>(pQKVf, pK16, M_ * NKV_ * 64);
    vhalf_kernel<<<((M_ * 512 / 4) + 255) / 256, 256>>>(pQKVf, pV16, M_ * 512 / 4);

    // Attention
    flash_fp16<<<dim3(S_ / 128, NH_, B_), 256, FA_SMEM>>>(
        pQh, pQl, pK16, pV16, pAh, pAl);

    // Output projection
    gemm_tc3<<<dim3(H_ / 128, M_ / 128), 256, GEMM_SMEM>>>(
        pAh, pAl, powh, powl, o_b, out, M_, H_, H_);
}

// round 6
// speedup vs baseline: 4.9580x; 1.0655x over previous
#include <cuda_runtime.h>
#include <cuda_bf16.h>
#include <cuda_fp16.h>
#include <math.h>
#include <stdint.h>

typedef __nv_bfloat16 bf16;
typedef __half fp16;

// Problem constants
#define B_    2
#define S_    2048
#define H_    2048
#define NH_   16
#define NKV_  4
#define HD_   128
#define M_    (B_ * S_)          // 4096
#define QW_   (NH_ * HD_)        // 2048
#define KVW_  (NKV_ * HD_)       // 512
#define NREP_ (NH_ / NKV_)       // 4
#define QKVW_ 3072               // merged Q|K|V width

// ---------------------------------------------------------------------------
// Scratch device globals
// ---------------------------------------------------------------------------
__device__ float g_QKVf[(size_t)M_ * QKVW_];   // fused projection out (fp32)
__device__ float g_qkvb[QKVW_];
__device__ bf16 g_Xh[(size_t)M_ * H_],  g_Xl[(size_t)M_ * H_];
__device__ bf16 g_wh[(size_t)QKVW_ * H_], g_wl[(size_t)QKVW_ * H_];   // merged qkv weights
__device__ bf16 g_owh[(size_t)H_ * QW_], g_owl[(size_t)H_ * QW_];
__device__ fp16 g_Q16[(size_t)M_ * QW_];                               // fp16 Q (roped)
__device__ fp16 g_K16[(size_t)M_ * KVW_];                              // fp16 K (roped)
__device__ fp16 g_V16[(size_t)M_ * KVW_];                              // fp16 V
__device__ bf16 g_Ah[(size_t)M_ * QW_],  g_Al[(size_t)M_ * QW_];       // attention out (split)
__device__ float g_cosT[S_ * 64];
__device__ float g_sinT[S_ * 64];

// ---------------------------------------------------------------------------
// Helpers
// ---------------------------------------------------------------------------
__device__ __forceinline__ uint32_t smem_u32(const void* p) {
    return (uint32_t)__cvta_generic_to_shared(p);
}
__device__ __forceinline__ void ldsm_x4(uint32_t* r, uint32_t a) {
    asm volatile("ldmatrix.sync.aligned.m8n8.x4.shared.b16 {%0,%1,%2,%3},[%4];"
        : "=r"(r[0]), "=r"(r[1]), "=r"(r[2]), "=r"(r[3]) : "r"(a));
}
__device__ __forceinline__ void ldsm_x4_t(uint32_t* r, uint32_t a) {
    asm volatile("ldmatrix.sync.aligned.m8n8.x4.trans.shared.b16 {%0,%1,%2,%3},[%4];"
        : "=r"(r[0]), "=r"(r[1]), "=r"(r[2]), "=r"(r[3]) : "r"(a));
}
__device__ __forceinline__ void mma_bf16(float* c, const uint32_t* a, uint32_t b0, uint32_t b1) {
    asm volatile(
        "mma.sync.aligned.m16n8k16.row.col.f32.bf16.bf16.f32 "
        "{%0,%1,%2,%3},{%4,%5,%6,%7},{%8,%9},{%0,%1,%2,%3};"
        : "+f"(c[0]), "+f"(c[1]), "+f"(c[2]), "+f"(c[3])
        : "r"(a[0]), "r"(a[1]), "r"(a[2]), "r"(a[3]), "r"(b0), "r"(b1));
}
__device__ __forceinline__ void mma_f16(float* c, const uint32_t* a, uint32_t b0, uint32_t b1) {
    asm volatile(
        "mma.sync.aligned.m16n8k16.row.col.f32.f16.f16.f32 "
        "{%0,%1,%2,%3},{%4,%5,%6,%7},{%8,%9},{%0,%1,%2,%3};"
        : "+f"(c[0]), "+f"(c[1]), "+f"(c[2]), "+f"(c[3])
        : "r"(a[0]), "r"(a[1]), "r"(a[2]), "r"(a[3]), "r"(b0), "r"(b1));
}
__device__ __forceinline__ uint32_t pack2(bf16 a, bf16 b) {
    uint16_t ua = *reinterpret_cast<uint16_t*>(&a);
    uint16_t ub = *reinterpret_cast<uint16_t*>(&b);
    return (uint32_t)ua | ((uint32_t)ub << 16);
}
__device__ __forceinline__ void split2(float x, float y, uint32_t& hi, uint32_t& lo) {
    bf16 hx = __float2bfloat16(x), hy = __float2bfloat16(y);
    float rx = x - __bfloat162float(hx);
    float ry = y - __bfloat162float(hy);
    hi = pack2(hx, hy);
    lo = pack2(__float2bfloat16(rx), __float2bfloat16(ry));
}
__device__ __forceinline__ uint32_t packh2(float a, float b) {
    __half2 h = __floats2half2_rn(a, b);
    return *reinterpret_cast<uint32_t*>(&h);
}
__device__ __forceinline__ void cp16(void* dst, const void* src) {
    uint32_t d = smem_u32(dst);
    asm volatile("cp.async.cg.shared.global [%0],[%1],16;" :: "r"(d), "l"(src));
}
__device__ __forceinline__ void cp_commit() {
    asm volatile("cp.async.commit_group;");
}
template <int N> __device__ __forceinline__ void cp_wait() {
    asm volatile("cp.async.wait_group %0;" :: "n"(N));
}

// ---------------------------------------------------------------------------
// Prep kernel 0: RoPE tables (double precision)
// ---------------------------------------------------------------------------
__global__ void rope_tables_kernel() {
    int idx = blockIdx.x * blockDim.x + threadIdx.x;
    if (idx >= S_ * 64) return;
    int s = idx >> 6, j = idx & 63;
    double inv_freq = exp(-((double)j / 64.0) * log(10000.0));
    double ang = (double)s * inv_freq;
    g_cosT[idx] = (float)cos(ang);
    g_sinT[idx] = (float)sin(ang);
}

// ---------------------------------------------------------------------------
// Prep kernel 1: split everything (X, q/k/v/o weights, biases) in ONE launch
// ---------------------------------------------------------------------------
#define N_X   (M_ * H_ / 4)                 // 2097152
#define N_QW  (QW_ * H_ / 4)                // 1048576
#define N_KW  (KVW_ * H_ / 4)               // 262144
#define N_VW  (KVW_ * H_ / 4)
#define N_OW  (H_ * QW_ / 4)
#define C1 (N_X)
#define C2 (C1 + N_QW)
#define C3 (C2 + N_KW)
#define C4 (C3 + N_VW)
#define C5 (C4 + N_OW)
#define C6 (C5 + QKVW_ / 4)                 // bias tail

__global__ void split_all_kernel(const float* __restrict__ X,
                                 const float* __restrict__ qw, const float* __restrict__ kw,
                                 const float* __restrict__ vw, const float* __restrict__ ow,
                                 const float* __restrict__ qb, const float* __restrict__ kb,
                                 const float* __restrict__ vb) {
    int i = blockIdx.x * blockDim.x + threadIdx.x;
    if (i >= C6) return;
    const float* src;
    bf16 *hi, *lo;
    int off;
    if (i < C1)      { src = X;  hi = g_Xh;  lo = g_Xl;  off = i; }
    else if (i < C2) { src = qw; hi = g_wh;  lo = g_wl;  off = i - C1; }
    else if (i < C3) { src = kw; hi = g_wh + (size_t)2048 * H_; lo = g_wl + (size_t)2048 * H_; off = i - C2; }
    else if (i < C4) { src = vw; hi = g_wh + (size_t)2560 * H_; lo = g_wl + (size_t)2560 * H_; off = i - C3; }
    else if (i < C5) { src = ow; hi = g_owh; lo = g_owl; off = i - C4; }
    else {
        int j = (i - C5) * 4;      // bias element base
#pragma unroll
        for (int t = 0; t < 4; t++) {
            int c = j + t;
            g_qkvb[c] = (c < 2048) ? qb[c] : (c < 2560 ? kb[c - 2048] : vb[c - 2560]);
        }
        return;
    }
    float4 v = ((const float4*)src)[off];
    uint32_t h0, h1, l0, l1;
    split2(v.x, v.y, h0, l0); split2(v.z, v.w, h1, l1);
    ((uint2*)hi)[off] = make_uint2(h0, h1);
    ((uint2*)lo)[off] = make_uint2(l0, l1);
}

// ---------------------------------------------------------------------------
// Prep kernel 3: RoPE Q -> single fp16
// ---------------------------------------------------------------------------
__global__ void rope_q_fp16(const float* __restrict__ QKVf, fp16* __restrict__ Q16, int total) {
    int idx = blockIdx.x * blockDim.x + threadIdx.x;
    if (idx >= total) return;
    int j = idx & 63;
    int t = idx >> 6;
    int h = t % NH_;
    int row = t / NH_;
    int s = row & (S_ - 1);
    float c  = g_cosT[s * 64 + j];
    float sn = g_sinT[s * 64 + j];
    size_t ib = (size_t)row * QKVW_ + h * HD_;
    size_t ob = (size_t)row * QW_ + h * HD_;
    float x1 = QKVf[ib + j];
    float x2 = QKVf[ib + j + 64];
    Q16[ob + j]      = __float2half_rn(x1 * c - x2 * sn);
    Q16[ob + j + 64] = __float2half_rn(x2 * c + x1 * sn);
}

// ---------------------------------------------------------------------------
// Prep kernel 4: RoPE K + V fp16 convert, one launch
// ---------------------------------------------------------------------------
#define RK_TOTAL (M_ * NKV_ * 64)           // 1048576
#define VH_TOTAL (M_ * 512 / 4)             // 524288

__global__ void rope_kv_kernel(const float* __restrict__ QKVf,
                               fp16* __restrict__ K16, fp16* __restrict__ V16) {
    int idx = blockIdx.x * blockDim.x + threadIdx.x;
    if (idx < RK_TOTAL) {
        int j = idx & 63;
        int t = idx >> 6;
        int h = t % NKV_;
        int row = t / NKV_;
        int s = row & (S_ - 1);
        float c  = g_cosT[s * 64 + j];
        float sn = g_sinT[s * 64 + j];
        size_t ib = (size_t)row * QKVW_ + 2048 + h * HD_;
        size_t ob = (size_t)row * KVW_ + h * HD_;
        float x1 = QKVf[ib + j];
        float x2 = QKVf[ib + j + 64];
        K16[ob + j]      = __float2half_rn(x1 * c - x2 * sn);
        K16[ob + j + 64] = __float2half_rn(x2 * c + x1 * sn);
    } else if (idx < RK_TOTAL + VH_TOTAL) {
        int i = idx - RK_TOTAL;
        int row = i >> 7;
        int c4 = (i & 127) * 4;
        float4 v = *(const float4*)&QKVf[(size_t)row * QKVW_ + 2560 + c4];
        uint2 o;
        o.x = packh2(v.x, v.y);
        o.y = packh2(v.z, v.w);
        *(uint2*)&V16[(size_t)row * KVW_ + c4] = o;
    }
}

// ---------------------------------------------------------------------------
// GEMM (pre-split bf16x3, cp.async 3-stage): C = A @ W^T + bias (fp32 out)
// BM=BN=128, BK=64, 256 threads, warp tile 64x32.
// ---------------------------------------------------------------------------
#define GS 72
#define GTILE (128 * GS)
#define GSTAGE (4 * GTILE)
#define GEMM_SMEM (3 * GSTAGE * 2)

__global__ __launch_bounds__(256, 1)
void gemm_tc3(const bf16* __restrict__ Agh, const bf16* __restrict__ Agl,
              const bf16* __restrict__ Bgh, const bf16* __restrict__ Bgl,
              const float* __restrict__ bias, float* __restrict__ C,
              int M, int N, int K) {
    extern __shared__ bf16 smg[];

    const int tid = threadIdx.x;
    const int lane = tid & 31, wid = tid >> 5;
    const int wm = wid >> 2, wn = wid & 3;
    const int bm = blockIdx.y * 128, bn = blockIdx.x * 128;

    const int arow = (lane & 7) + ((lane >> 3) & 1) * 8;
    const int acol = ((lane >> 4) & 1) * 8;
    const int brow = (lane & 7) + ((lane >> 4) & 1) * 8;
    const int bcol = ((lane >> 3) & 1) * 8;

    float acc[4][4][4];
#pragma unroll
    for (int i = 0; i < 4; i++)
#pragma unroll
        for (int j = 0; j < 4; j++)
#pragma unroll
            for (int k = 0; k < 4; k++) acc[i][j][k] = 0.f;

    const int nIter = K / 64;

    auto issue_stage = [&](int t) {
        if (t < nIter) {
            const int k0 = t * 64;
            bf16* sb = smg + (t % 3) * GSTAGE;
#pragma unroll
            for (int i = 0; i < 16; i++) {
                int id = i * 256 + tid;
                int tile = id >> 10;
                int rem = id & 1023;
                int r = rem >> 3, ch = rem & 7;
                const bf16* src;
                if (tile == 0)      src = Agh + (size_t)(bm + r) * K + k0 + ch * 8;
                else if (tile == 1) src = Agl + (size_t)(bm + r) * K + k0 + ch * 8;
                else if (tile == 2) src = Bgh + (size_t)(bn + r) * K + k0 + ch * 8;
                else                src = Bgl + (size_t)(bn + r) * K + k0 + ch * 8;
                cp16(sb + tile * GTILE + r * GS + ch * 8, src);
            }
        }
        cp_commit();
    };

    issue_stage(0);
    issue_stage(1);

    for (int t = 0; t < nIter; t++) {
        cp_wait<1>();
        __syncthreads();
        issue_stage(t + 2);

        const bf16* pAh = smg + (t % 3) * GSTAGE;
        const bf16* pAl = pAh + GTILE;
        const bf16* pBh = pAl + GTILE;
        const bf16* pBl = pBh + GTILE;

#pragma unroll
        for (int kk = 0; kk < 64; kk += 16) {
            uint32_t fah[4][4], fal[4][4], fbh[2][4], fbl[2][4];
#pragma unroll
            for (int mt = 0; mt < 4; mt++) {
                int r = wm * 64 + mt * 16 + arow;
                ldsm_x4(fah[mt], smem_u32(pAh + r * GS + kk + acol));
                ldsm_x4(fal[mt], smem_u32(pAl + r * GS + kk + acol));
            }
#pragma unroll
            for (int np = 0; np < 2; np++) {
                int r = wn * 32 + np * 16 + brow;
                ldsm_x4(fbh[np], smem_u32(pBh + r * GS + kk + bcol));
                ldsm_x4(fbl[np], smem_u32(pBl + r * GS + kk + bcol));
            }
#pragma unroll
            for (int mt = 0; mt < 4; mt++) {
#pragma unroll
                for (int nt = 0; nt < 4; nt++) {
                    int np = nt >> 1, hf = (nt & 1) * 2;
                    mma_bf16(acc[mt][nt], fah[mt], fbh[np][hf], fbh[np][hf + 1]);
                    mma_bf16(acc[mt][nt], fal[mt], fbh[np][hf], fbh[np][hf + 1]);
                    mma_bf16(acc[mt][nt], fah[mt], fbl[np][hf], fbl[np][hf + 1]);
                }
            }
        }
    }

    const int g = lane >> 2, c2 = (lane & 3) * 2;
#pragma unroll
    for (int mt = 0; mt < 4; mt++) {
        int row = bm + wm * 64 + mt * 16 + g;
#pragma unroll
        for (int nt = 0; nt < 4; nt++) {
            int col = bn + wn * 32 + nt * 8 + c2;
            float b0 = bias[col], b1 = bias[col + 1];
            *(float2*)&C[(size_t)row * N + col] =
                make_float2(acc[mt][nt][0] + b0, acc[mt][nt][1] + b1);
            *(float2*)&C[(size_t)(row + 8) * N + col] =
                make_float2(acc[mt][nt][2] + b0, acc[mt][nt][3] + b1);
        }
    }
}

// ---------------------------------------------------------------------------
// Flash attention, single-fp16 operands, 4-stage KV ring.
// CTA: 128 q-rows x 1 head, 8 warps x 16 rows. Q fragments in registers.
// Per key tile (per warp): S = 64 mma, PV = 64 mma.
// ---------------------------------------------------------------------------
#define FQS 136                            // fp16 row stride (128 + 8)
#define FQ_TILE (128 * FQS)                // Q tile (17408 elems = 34816 B)
#define FKV_TILE (64 * FQS)                // one K or V tile
#define FKV_STAGE (2 * FKV_TILE)           // K + V  (17408 elems)
#define FA_NSTAGE 4
#define FA_SMEM ((FQ_TILE + FA_NSTAGE * FKV_STAGE) * 2)   // 174080 B

__global__ __launch_bounds__(256, 1)
void flash_fp16(const fp16* __restrict__ Q_g,
                const fp16* __restrict__ K_g, const fp16* __restrict__ V_g,
                bf16* __restrict__ Oh_g, bf16* __restrict__ Ol_g) {
    extern __shared__ fp16 smf[];
    fp16* sQ = smf;
    fp16* stage0 = sQ + FQ_TILE;

    const int tid = threadIdx.x, lane = tid & 31, wid = tid >> 5;
    const int qt = blockIdx.x, h = blockIdx.y, b = blockIdx.z;
    const int kvh = h / NREP_;
    const float scale = 0.08838834764831845f;

    const int g = lane >> 2;
    const int arow = (lane & 7) + ((lane >> 3) & 1) * 8;
    const int acol = ((lane >> 4) & 1) * 8;
    const int brow = (lane & 7) + ((lane >> 4) & 1) * 8;
    const int bcol = ((lane >> 3) & 1) * 8;
    const int vrow = (lane & 7) + ((lane >> 3) & 1) * 8;
    const int vcol = ((lane >> 4) & 1) * 8;

    // ---- prologue: Q (own group), then KV stages 0..2 ----
    const size_t qb = ((size_t)(b * S_ + qt * 128)) * QW_ + (size_t)h * HD_;
#pragma unroll
    for (int i = 0; i < 8; i++) {
        int id = i * 256 + tid;            // 0..2047
        int r = id >> 4, ch = id & 15;
        cp16(sQ + r * FQS + ch * 8, Q_g + qb + (size_t)r * QW_ + ch * 8);
    }
    cp_commit();

    auto issue_kv = [&](int kt) {
        if (kt < S_ / 64) {
            const size_t kb = ((size_t)(b * S_ + kt * 64)) * KVW_ + (size_t)kvh * HD_;
            fp16* sb = stage0 + (kt % FA_NSTAGE) * FKV_STAGE;
#pragma unroll
            for (int i = 0; i < 8; i++) {
                int id = i * 256 + tid;
                int tile = id >> 10;       // 0:K 1:V
                int rem = id & 1023;
                int r = rem >> 4, ch = rem & 15;
                const fp16* src = (tile ? V_g : K_g) + kb + (size_t)r * KVW_ + ch * 8;
                cp16(sb + tile * FKV_TILE + r * FQS + ch * 8, src);
            }
        }
        cp_commit();
    };
    issue_kv(0);
    issue_kv(1);
    issue_kv(2);

    // ---- Q fragment preload into registers ----
    cp_wait<3>();          // Q group retired
    __syncthreads();
    uint32_t qf[8][4];
#pragma unroll
    for (int kc = 0; kc < 8; kc++) {
        int r = wid * 16 + arow;
        ldsm_x4(qf[kc], smem_u32(sQ + r * FQS + kc * 16 + acol));
    }

    float m_[2] = {-INFINITY, -INFINITY};
    float l_[2] = {0.f, 0.f};
    float oacc[16][4];
#pragma unroll
    for (int i = 0; i < 16; i++)
#pragma unroll
        for (int j = 0; j < 4; j++) oacc[i][j] = 0.f;

    const int NT = S_ / 64;
    for (int kt = 0; kt < NT; kt++) {
        cp_wait<2>();
        __syncthreads();
        issue_kv(kt + 3);

        const fp16* sK = stage0 + (kt % FA_NSTAGE) * FKV_STAGE;
        const fp16* sV = sK + FKV_TILE;

        // ---- S = Q @ K^T (single fp16) ----
        float sacc[8][4];
#pragma unroll
        for (int i = 0; i < 8; i++)
#pragma unroll
            for (int j = 0; j < 4; j++) sacc[i][j] = 0.f;

#pragma unroll
        for (int kc = 0; kc < 8; kc++) {
            uint32_t kb_[4][4];
#pragma unroll
            for (int ng = 0; ng < 4; ng++) {
                int r = ng * 16 + brow;
                ldsm_x4(kb_[ng], smem_u32(sK + r * FQS + kc * 16 + bcol));
            }
#pragma unroll
            for (int nt = 0; nt < 8; nt++) {
                int np = nt >> 1, hf = (nt & 1) * 2;
                mma_f16(sacc[nt], qf[kc], kb_[np][hf], kb_[np][hf + 1]);
            }
        }

        // ---- online softmax (registers + shuffles) ----
        float mx0 = m_[0], mx1 = m_[1];
#pragma unroll
        for (int nt = 0; nt < 8; nt++) {
            mx0 = fmaxf(mx0, fmaxf(sacc[nt][0], sacc[nt][1]) * scale);
            mx1 = fmaxf(mx1, fmaxf(sacc[nt][2], sacc[nt][3]) * scale);
        }
        mx0 = fmaxf(mx0, __shfl_xor_sync(0xffffffff, mx0, 1));
        mx0 = fmaxf(mx0, __shfl_xor_sync(0xffffffff, mx0, 2));
        mx1 = fmaxf(mx1, __shfl_xor_sync(0xffffffff, mx1, 1));
        mx1 = fmaxf(mx1, __shfl_xor_sync(0xffffffff, mx1, 2));
        float al0 = __expf(m_[0] - mx0);
        float al1 = __expf(m_[1] - mx1);
        m_[0] = mx0; m_[1] = mx1;

        uint32_t pf[8][2];
        float rs0 = 0.f, rs1 = 0.f;
#pragma unroll
        for (int nt = 0; nt < 8; nt++) {
            float p0 = __expf(sacc[nt][0] * scale - mx0);
            float p1 = __expf(sacc[nt][1] * scale - mx0);
            float p2 = __expf(sacc[nt][2] * scale - mx1);
            float p3 = __expf(sacc[nt][3] * scale - mx1);
            rs0 += p0 + p1; rs1 += p2 + p3;
            pf[nt][0] = packh2(p0, p1);
            pf[nt][1] = packh2(p2, p3);
        }
        rs0 += __shfl_xor_sync(0xffffffff, rs0, 1);
        rs0 += __shfl_xor_sync(0xffffffff, rs0, 2);
        rs1 += __shfl_xor_sync(0xffffffff, rs1, 1);
        rs1 += __shfl_xor_sync(0xffffffff, rs1, 2);
        l_[0] = l_[0] * al0 + rs0;
        l_[1] = l_[1] * al1 + rs1;

#pragma unroll
        for (int nt = 0; nt < 16; nt++) {
            oacc[nt][0] *= al0; oacc[nt][1] *= al0;
            oacc[nt][2] *= al1; oacc[nt][3] *= al1;
        }

        // ---- O += P(fp16) @ V(fp16) ----
#pragma unroll
        for (int kc = 0; kc < 4; kc++) {
            uint32_t ah[4] = {pf[2 * kc][0], pf[2 * kc][1], pf[2 * kc + 1][0], pf[2 * kc + 1][1]};
#pragma unroll
            for (int dh = 0; dh < 2; dh++) {
                uint32_t vb_[4][4];
#pragma unroll
                for (int ng = 0; ng < 4; ng++) {
                    int cbase = dh * 64 + ng * 16;
                    ldsm_x4_t(vb_[ng], smem_u32(sV + (kc * 16 + vrow) * FQS + cbase + vcol));
                }
#pragma unroll
                for (int nt = 0; nt < 8; nt++) {
                    int np = nt >> 1, hf = (nt & 1) * 2;
                    mma_f16(oacc[dh * 8 + nt], ah, vb_[np][hf], vb_[np][hf + 1]);
                }
            }
        }
    }

    // ---- epilogue: normalize, split to bf16 hi/lo, store ----
    float inv0 = 1.f / (l_[0] + 1e-10f);
    float inv1 = 1.f / (l_[1] + 1e-10f);
    const int c2 = (lane & 3) * 2;
    const size_t ob = ((size_t)(b * S_ + qt * 128 + wid * 16 + g)) * QW_ + (size_t)h * HD_;
#pragma unroll
    for (int nt = 0; nt < 16; nt++) {
        int col = nt * 8 + c2;
        uint32_t h0, l0, h1, l1;
        split2(oacc[nt][0] * inv0, oacc[nt][1] * inv0, h0, l0);
        split2(oacc[nt][2] * inv1, oacc[nt][3] * inv1, h1, l1);
        *(uint32_t*)&Oh_g[ob + col] = h0;
        *(uint32_t*)&Ol_g[ob + col] = l0;
        *(uint32_t*)&Oh_g[ob + 8 * QW_ + col] = h1;
        *(uint32_t*)&Ol_g[ob + 8 * QW_ + col] = l1;
    }
}

// ---------------------------------------------------------------------------
// Launch — order chosen so launch index 5 (ncu -s 5 -c 1) is flash_fp16
// ---------------------------------------------------------------------------
extern "C" void kernel_launch(void* const* d_in, const int* in_sizes, int n_in,
                              void* d_out, int out_size) {
    const float* X   = (const float*)d_in[0];
    const float* q_w = (const float*)d_in[1];
    const float* q_b = (const float*)d_in[2];
    const float* k_w = (const float*)d_in[3];
    const float* k_b = (const float*)d_in[4];
    const float* v_w = (const float*)d_in[5];
    const float* v_b = (const float*)d_in[6];
    const float* o_w = (const float*)d_in[7];
    const float* o_b = (const float*)d_in[8];
    float* out = (float*)d_out;

    float *pQKVf, *pqkvb;
    bf16 *pXh, *pXl, *pwh, *pwl, *powh, *powl, *pAh, *pAl;
    fp16 *pQ16, *pK16, *pV16;
    cudaGetSymbolAddress((void**)&pQKVf, g_QKVf);
    cudaGetSymbolAddress((void**)&pqkvb, g_qkvb);
    cudaGetSymbolAddress((void**)&pXh, g_Xh);   cudaGetSymbolAddress((void**)&pXl, g_Xl);
    cudaGetSymbolAddress((void**)&pwh, g_wh);   cudaGetSymbolAddress((void**)&pwl, g_wl);
    cudaGetSymbolAddress((void**)&powh, g_owh); cudaGetSymbolAddress((void**)&powl, g_owl);
    cudaGetSymbolAddress((void**)&pAh, g_Ah);   cudaGetSymbolAddress((void**)&pAl, g_Al);
    cudaGetSymbolAddress((void**)&pQ16, g_Q16);
    cudaGetSymbolAddress((void**)&pK16, g_K16); cudaGetSymbolAddress((void**)&pV16, g_V16);

    cudaFuncSetAttribute(gemm_tc3, cudaFuncAttributeMaxDynamicSharedMemorySize, GEMM_SMEM);
    cudaFuncSetAttribute(flash_fp16, cudaFuncAttributeMaxDynamicSharedMemorySize, FA_SMEM);

    // launch 0: RoPE tables
    rope_tables_kernel<<<(S_ * 64 + 255) / 256, 256>>>();
    // launch 1: all splits + bias concat
    split_all_kernel<<<(C6 + 255) / 256, 256>>>(X, q_w, k_w, v_w, o_w, q_b, k_b, v_b);
    // launch 2: fused QKV projection
    gemm_tc3<<<dim3(QKVW_ / 128, M_ / 128), 256, GEMM_SMEM>>>(
        pXh, pXl, pwh, pwl, pqkvb, pQKVf, M_, QKVW_, H_);
    // launch 3: RoPE Q
    rope_q_fp16<<<(M_ * NH_ * 64 + 255) / 256, 256>>>(pQKVf, pQ16, M_ * NH_ * 64);
    // launch 4: RoPE K + V convert
    rope_kv_kernel<<<(RK_TOTAL + VH_TOTAL + 255) / 256, 256>>>(pQKVf, pK16, pV16);
    // launch 5: flash attention  <- ncu captures this one
    flash_fp16<<<dim3(S_ / 128, NH_, B_), 256, FA_SMEM>>>(
        pQ16, pK16, pV16, pAh, pAl);
    // launch 6: output projection
    gemm_tc3<<<dim3(H_ / 128, M_ / 128), 256, GEMM_SMEM>>>(
        pAh, pAl, powh, powl, o_b, out, M_, H_, H_);
}

// round 7
// speedup vs baseline: 5.1404x; 1.0368x over previous
#include <cuda_runtime.h>
#include <cuda_bf16.h>
#include <cuda_fp16.h>
#include <math.h>
#include <stdint.h>

typedef __nv_bfloat16 bf16;
typedef __half fp16;

// Problem constants
#define B_    2
#define S_    2048
#define H_    2048
#define NH_   16
#define NKV_  4
#define HD_   128
#define M_    (B_ * S_)          // 4096
#define QW_   (NH_ * HD_)        // 2048
#define KVW_  (NKV_ * HD_)       // 512
#define NREP_ (NH_ / NKV_)       // 4
#define QKVW_ 3072

// ---------------------------------------------------------------------------
// Scratch device globals
// ---------------------------------------------------------------------------
__device__ float g_QKVf[(size_t)M_ * QKVW_];
__device__ float g_qkvb[QKVW_];
__device__ bf16 g_Xh[(size_t)M_ * H_],  g_Xl[(size_t)M_ * H_];
__device__ bf16 g_wh[(size_t)QKVW_ * H_], g_wl[(size_t)QKVW_ * H_];
__device__ bf16 g_owh[(size_t)H_ * QW_], g_owl[(size_t)H_ * QW_];
__device__ fp16 g_Q16[(size_t)M_ * QW_];
__device__ fp16 g_K16[(size_t)M_ * KVW_];
__device__ fp16 g_V16[(size_t)M_ * KVW_];
__device__ bf16 g_Ah[(size_t)M_ * QW_],  g_Al[(size_t)M_ * QW_];
__device__ float g_cosT[S_ * 64];
__device__ float g_sinT[S_ * 64];

// ---------------------------------------------------------------------------
// Helpers
// ---------------------------------------------------------------------------
__device__ __forceinline__ uint32_t smem_u32(const void* p) {
    return (uint32_t)__cvta_generic_to_shared(p);
}
__device__ __forceinline__ void ldsm_x4(uint32_t* r, uint32_t a) {
    asm volatile("ldmatrix.sync.aligned.m8n8.x4.shared.b16 {%0,%1,%2,%3},[%4];"
        : "=r"(r[0]), "=r"(r[1]), "=r"(r[2]), "=r"(r[3]) : "r"(a));
}
__device__ __forceinline__ void ldsm_x4_t(uint32_t* r, uint32_t a) {
    asm volatile("ldmatrix.sync.aligned.m8n8.x4.trans.shared.b16 {%0,%1,%2,%3},[%4];"
        : "=r"(r[0]), "=r"(r[1]), "=r"(r[2]), "=r"(r[3]) : "r"(a));
}
__device__ __forceinline__ void mma_bf16(float* c, const uint32_t* a, uint32_t b0, uint32_t b1) {
    asm volatile(
        "mma.sync.aligned.m16n8k16.row.col.f32.bf16.bf16.f32 "
        "{%0,%1,%2,%3},{%4,%5,%6,%7},{%8,%9},{%0,%1,%2,%3};"
        : "+f"(c[0]), "+f"(c[1]), "+f"(c[2]), "+f"(c[3])
        : "r"(a[0]), "r"(a[1]), "r"(a[2]), "r"(a[3]), "r"(b0), "r"(b1));
}
__device__ __forceinline__ void mma_f16(float* c, const uint32_t* a, uint32_t b0, uint32_t b1) {
    asm volatile(
        "mma.sync.aligned.m16n8k16.row.col.f32.f16.f16.f32 "
        "{%0,%1,%2,%3},{%4,%5,%6,%7},{%8,%9},{%0,%1,%2,%3};"
        : "+f"(c[0]), "+f"(c[1]), "+f"(c[2]), "+f"(c[3])
        : "r"(a[0]), "r"(a[1]), "r"(a[2]), "r"(a[3]), "r"(b0), "r"(b1));
}
__device__ __forceinline__ uint32_t pack2(bf16 a, bf16 b) {
    uint16_t ua = *reinterpret_cast<uint16_t*>(&a);
    uint16_t ub = *reinterpret_cast<uint16_t*>(&b);
    return (uint32_t)ua | ((uint32_t)ub << 16);
}
__device__ __forceinline__ void split2(float x, float y, uint32_t& hi, uint32_t& lo) {
    bf16 hx = __float2bfloat16(x), hy = __float2bfloat16(y);
    float rx = x - __bfloat162float(hx);
    float ry = y - __bfloat162float(hy);
    hi = pack2(hx, hy);
    lo = pack2(__float2bfloat16(rx), __float2bfloat16(ry));
}
__device__ __forceinline__ uint32_t packh2(float a, float b) {
    __half2 h = __floats2half2_rn(a, b);
    return *reinterpret_cast<uint32_t*>(&h);
}
__device__ __forceinline__ void cp16(void* dst, const void* src) {
    uint32_t d = smem_u32(dst);
    asm volatile("cp.async.cg.shared.global [%0],[%1],16;" :: "r"(d), "l"(src));
}
__device__ __forceinline__ void cp_commit() {
    asm volatile("cp.async.commit_group;");
}
template <int N> __device__ __forceinline__ void cp_wait() {
    asm volatile("cp.async.wait_group %0;" :: "n"(N));
}

// ---------------------------------------------------------------------------
// Prep kernel A: RoPE tables + all splits + bias concat, ONE launch
// ---------------------------------------------------------------------------
#define TBL_N (S_ * 64)
#define N_X   (M_ * H_ / 4)
#define N_QW  (QW_ * H_ / 4)
#define N_KW  (KVW_ * H_ / 4)
#define N_VW  (KVW_ * H_ / 4)
#define N_OW  (H_ * QW_ / 4)
#define C1 (N_X)
#define C2 (C1 + N_QW)
#define C3 (C2 + N_KW)
#define C4 (C3 + N_VW)
#define C5 (C4 + N_OW)
#define C6 (C5 + QKVW_ / 4)
#define PREP_TOTAL (TBL_N + C6)

__global__ void prep_all_kernel(const float* __restrict__ X,
                                const float* __restrict__ qw, const float* __restrict__ kw,
                                const float* __restrict__ vw, const float* __restrict__ ow,
                                const float* __restrict__ qb, const float* __restrict__ kb,
                                const float* __restrict__ vb) {
    int idx = blockIdx.x * blockDim.x + threadIdx.x;
    if (idx >= PREP_TOTAL) return;
    if (idx < TBL_N) {
        int s = idx >> 6, j = idx & 63;
        double inv_freq = exp(-((double)j / 64.0) * log(10000.0));
        double ang = (double)s * inv_freq;
        g_cosT[idx] = (float)cos(ang);
        g_sinT[idx] = (float)sin(ang);
        return;
    }
    int i = idx - TBL_N;
    const float* src;
    bf16 *hi, *lo;
    int off;
    if (i < C1)      { src = X;  hi = g_Xh;  lo = g_Xl;  off = i; }
    else if (i < C2) { src = qw; hi = g_wh;  lo = g_wl;  off = i - C1; }
    else if (i < C3) { src = kw; hi = g_wh + (size_t)2048 * H_; lo = g_wl + (size_t)2048 * H_; off = i - C2; }
    else if (i < C4) { src = vw; hi = g_wh + (size_t)2560 * H_; lo = g_wl + (size_t)2560 * H_; off = i - C3; }
    else if (i < C5) { src = ow; hi = g_owh; lo = g_owl; off = i - C4; }
    else {
        int j = (i - C5) * 4;
#pragma unroll
        for (int t = 0; t < 4; t++) {
            int c = j + t;
            g_qkvb[c] = (c < 2048) ? qb[c] : (c < 2560 ? kb[c - 2048] : vb[c - 2560]);
        }
        return;
    }
    float4 v = ((const float4*)src)[off];
    uint32_t h0, h1, l0, l1;
    split2(v.x, v.y, h0, l0); split2(v.z, v.w, h1, l1);
    ((uint2*)hi)[off] = make_uint2(h0, h1);
    ((uint2*)lo)[off] = make_uint2(l0, l1);
}

// ---------------------------------------------------------------------------
// Prep kernel B: RoPE Q + RoPE K + V fp16 convert, ONE launch
// ---------------------------------------------------------------------------
#define RQ_TOTAL (M_ * NH_ * 64)            // 4194304
#define RK_TOTAL (M_ * NKV_ * 64)           // 1048576
#define VH_TOTAL (M_ * 512 / 4)             // 524288
#define ROPE_TOTAL (RQ_TOTAL + RK_TOTAL + VH_TOTAL)

__global__ void rope_all_kernel(const float* __restrict__ QKVf,
                                fp16* __restrict__ Q16, fp16* __restrict__ K16,
                                fp16* __restrict__ V16) {
    int idx = blockIdx.x * blockDim.x + threadIdx.x;
    if (idx < RQ_TOTAL) {
        int j = idx & 63;
        int t = idx >> 6;
        int h = t % NH_;
        int row = t / NH_;
        int s = row & (S_ - 1);
        float c  = g_cosT[s * 64 + j];
        float sn = g_sinT[s * 64 + j];
        size_t ib = (size_t)row * QKVW_ + h * HD_;
        size_t ob = (size_t)row * QW_ + h * HD_;
        float x1 = QKVf[ib + j];
        float x2 = QKVf[ib + j + 64];
        Q16[ob + j]      = __float2half_rn(x1 * c - x2 * sn);
        Q16[ob + j + 64] = __float2half_rn(x2 * c + x1 * sn);
    } else if (idx < RQ_TOTAL + RK_TOTAL) {
        int id = idx - RQ_TOTAL;
        int j = id & 63;
        int t = id >> 6;
        int h = t % NKV_;
        int row = t / NKV_;
        int s = row & (S_ - 1);
        float c  = g_cosT[s * 64 + j];
        float sn = g_sinT[s * 64 + j];
        size_t ib = (size_t)row * QKVW_ + 2048 + h * HD_;
        size_t ob = (size_t)row * KVW_ + h * HD_;
        float x1 = QKVf[ib + j];
        float x2 = QKVf[ib + j + 64];
        K16[ob + j]      = __float2half_rn(x1 * c - x2 * sn);
        K16[ob + j + 64] = __float2half_rn(x2 * c + x1 * sn);
    } else if (idx < ROPE_TOTAL) {
        int i = idx - RQ_TOTAL - RK_TOTAL;
        int row = i >> 7;
        int c4 = (i & 127) * 4;
        float4 v = *(const float4*)&QKVf[(size_t)row * QKVW_ + 2560 + c4];
        uint2 o;
        o.x = packh2(v.x, v.y);
        o.y = packh2(v.z, v.w);
        *(uint2*)&V16[(size_t)row * KVW_ + c4] = o;
    }
}

// ---------------------------------------------------------------------------
// GEMM (pre-split bf16x3, cp.async 3-stage): C = A @ W^T + bias (fp32 out)
// ---------------------------------------------------------------------------
#define GS 72
#define GTILE (128 * GS)
#define GSTAGE (4 * GTILE)
#define GEMM_SMEM (3 * GSTAGE * 2)

__global__ __launch_bounds__(256, 1)
void gemm_tc3(const bf16* __restrict__ Agh, const bf16* __restrict__ Agl,
              const bf16* __restrict__ Bgh, const bf16* __restrict__ Bgl,
              const float* __restrict__ bias, float* __restrict__ C,
              int M, int N, int K) {
    extern __shared__ bf16 smg[];

    const int tid = threadIdx.x;
    const int lane = tid & 31, wid = tid >> 5;
    const int wm = wid >> 2, wn = wid & 3;
    const int bm = blockIdx.y * 128, bn = blockIdx.x * 128;

    const int arow = (lane & 7) + ((lane >> 3) & 1) * 8;
    const int acol = ((lane >> 4) & 1) * 8;
    const int brow = (lane & 7) + ((lane >> 4) & 1) * 8;
    const int bcol = ((lane >> 3) & 1) * 8;

    float acc[4][4][4];
#pragma unroll
    for (int i = 0; i < 4; i++)
#pragma unroll
        for (int j = 0; j < 4; j++)
#pragma unroll
            for (int k = 0; k < 4; k++) acc[i][j][k] = 0.f;

    const int nIter = K / 64;

    auto issue_stage = [&](int t) {
        if (t < nIter) {
            const int k0 = t * 64;
            bf16* sb = smg + (t % 3) * GSTAGE;
#pragma unroll
            for (int i = 0; i < 16; i++) {
                int id = i * 256 + tid;
                int tile = id >> 10;
                int rem = id & 1023;
                int r = rem >> 3, ch = rem & 7;
                const bf16* src;
                if (tile == 0)      src = Agh + (size_t)(bm + r) * K + k0 + ch * 8;
                else if (tile == 1) src = Agl + (size_t)(bm + r) * K + k0 + ch * 8;
                else if (tile == 2) src = Bgh + (size_t)(bn + r) * K + k0 + ch * 8;
                else                src = Bgl + (size_t)(bn + r) * K + k0 + ch * 8;
                cp16(sb + tile * GTILE + r * GS + ch * 8, src);
            }
        }
        cp_commit();
    };

    issue_stage(0);
    issue_stage(1);

    for (int t = 0; t < nIter; t++) {
        cp_wait<1>();
        __syncthreads();
        issue_stage(t + 2);

        const bf16* pAh = smg + (t % 3) * GSTAGE;
        const bf16* pAl = pAh + GTILE;
        const bf16* pBh = pAl + GTILE;
        const bf16* pBl = pBh + GTILE;

#pragma unroll
        for (int kk = 0; kk < 64; kk += 16) {
            uint32_t fah[4][4], fal[4][4], fbh[2][4], fbl[2][4];
#pragma unroll
            for (int mt = 0; mt < 4; mt++) {
                int r = wm * 64 + mt * 16 + arow;
                ldsm_x4(fah[mt], smem_u32(pAh + r * GS + kk + acol));
                ldsm_x4(fal[mt], smem_u32(pAl + r * GS + kk + acol));
            }
#pragma unroll
            for (int np = 0; np < 2; np++) {
                int r = wn * 32 + np * 16 + brow;
                ldsm_x4(fbh[np], smem_u32(pBh + r * GS + kk + bcol));
                ldsm_x4(fbl[np], smem_u32(pBl + r * GS + kk + bcol));
            }
#pragma unroll
            for (int mt = 0; mt < 4; mt++) {
#pragma unroll
                for (int nt = 0; nt < 4; nt++) {
                    int np = nt >> 1, hf = (nt & 1) * 2;
                    mma_bf16(acc[mt][nt], fah[mt], fbh[np][hf], fbh[np][hf + 1]);
                    mma_bf16(acc[mt][nt], fal[mt], fbh[np][hf], fbh[np][hf + 1]);
                    mma_bf16(acc[mt][nt], fah[mt], fbl[np][hf], fbl[np][hf + 1]);
                }
            }
        }
    }

    const int g = lane >> 2, c2 = (lane & 3) * 2;
#pragma unroll
    for (int mt = 0; mt < 4; mt++) {
        int row = bm + wm * 64 + mt * 16 + g;
#pragma unroll
        for (int nt = 0; nt < 4; nt++) {
            int col = bn + wn * 32 + nt * 8 + c2;
            float b0 = bias[col], b1 = bias[col + 1];
            *(float2*)&C[(size_t)row * N + col] =
                make_float2(acc[mt][nt][0] + b0, acc[mt][nt][1] + b1);
            *(float2*)&C[(size_t)(row + 8) * N + col] =
                make_float2(acc[mt][nt][2] + b0, acc[mt][nt][3] + b1);
        }
    }
}

// ---------------------------------------------------------------------------
// Flash attention v2: 128 threads (4 warps x 16 q-rows = 64 q-rows/CTA),
// Q fragments LDG'd straight from global (no Q smem), 3-stage KV ring,
// 2 CTAs/SM so one CTA's mma fills the other's softmax bubbles.
// ---------------------------------------------------------------------------
#define FQS 136
#define FKV_TILE (64 * FQS)
#define FKV_STAGE (2 * FKV_TILE)
#define FA_NSTAGE 3
#define FA_SMEM (FA_NSTAGE * FKV_STAGE * 2)   // 104448 B

__global__ __launch_bounds__(128, 2)
void flash_fp16(const fp16* __restrict__ Q_g,
                const fp16* __restrict__ K_g, const fp16* __restrict__ V_g,
                bf16* __restrict__ Oh_g, bf16* __restrict__ Ol_g) {
    extern __shared__ fp16 smf[];
    fp16* stage0 = smf;

    const int tid = threadIdx.x, lane = tid & 31, wid = tid >> 5;
    const int qt = blockIdx.x, h = blockIdx.y, b = blockIdx.z;
    const int kvh = h / NREP_;
    const float scale = 0.08838834764831845f;

    const int g = lane >> 2;
    const int brow = (lane & 7) + ((lane >> 4) & 1) * 8;
    const int bcol = ((lane >> 3) & 1) * 8;
    const int vrow = (lane & 7) + ((lane >> 3) & 1) * 8;
    const int vcol = ((lane >> 4) & 1) * 8;

    auto issue_kv = [&](int kt) {
        if (kt < S_ / 64) {
            const size_t kb = ((size_t)(b * S_ + kt * 64)) * KVW_ + (size_t)kvh * HD_;
            fp16* sb = stage0 + (kt % FA_NSTAGE) * FKV_STAGE;
#pragma unroll
            for (int i = 0; i < 16; i++) {
                int id = i * 128 + tid;    // 0..2047
                int tile = id >> 10;       // 0:K 1:V
                int rem = id & 1023;
                int r = rem >> 4, ch = rem & 15;
                const fp16* src = (tile ? V_g : K_g) + kb + (size_t)r * KVW_ + ch * 8;
                cp16(sb + tile * FKV_TILE + r * FQS + ch * 8, src);
            }
        }
        cp_commit();
    };
    issue_kv(0);
    issue_kv(1);
    issue_kv(2);

    // ---- Q fragments: direct LDG from global in mma layout ----
    const size_t qb = ((size_t)(b * S_ + qt * 64)) * QW_ + (size_t)h * HD_;
    uint32_t qf[8][4];
    {
        const int r0 = wid * 16 + g;
        const int c0 = (lane & 3) * 2;
#pragma unroll
        for (int kc = 0; kc < 8; kc++) {
#pragma unroll
            for (int i = 0; i < 4; i++) {
                int r = r0 + (i & 1) * 8;
                int c = kc * 16 + c0 + (i >> 1) * 8;
                qf[kc][i] = *(const uint32_t*)&Q_g[qb + (size_t)r * QW_ + c];
            }
        }
    }

    float m_[2] = {-INFINITY, -INFINITY};
    float l_[2] = {0.f, 0.f};
    float oacc[16][4];
#pragma unroll
    for (int i = 0; i < 16; i++)
#pragma unroll
        for (int j = 0; j < 4; j++) oacc[i][j] = 0.f;

    const int NT = S_ / 64;
    for (int kt = 0; kt < NT; kt++) {
        cp_wait<2>();
        __syncthreads();

        const fp16* sK = stage0 + (kt % FA_NSTAGE) * FKV_STAGE;
        const fp16* sV = sK + FKV_TILE;

        // ---- S = Q @ K^T ----
        float sacc[8][4];
#pragma unroll
        for (int i = 0; i < 8; i++)
#pragma unroll
            for (int j = 0; j < 4; j++) sacc[i][j] = 0.f;

#pragma unroll
        for (int kc = 0; kc < 8; kc++) {
            uint32_t kb_[4][4];
#pragma unroll
            for (int ng = 0; ng < 4; ng++) {
                int r = ng * 16 + brow;
                ldsm_x4(kb_[ng], smem_u32(sK + r * FQS + kc * 16 + bcol));
            }
#pragma unroll
            for (int nt = 0; nt < 8; nt++) {
                int np = nt >> 1, hf = (nt & 1) * 2;
                mma_f16(sacc[nt], qf[kc], kb_[np][hf], kb_[np][hf + 1]);
            }
        }

        // ---- online softmax ----
        float mx0 = m_[0], mx1 = m_[1];
#pragma unroll
        for (int nt = 0; nt < 8; nt++) {
            mx0 = fmaxf(mx0, fmaxf(sacc[nt][0], sacc[nt][1]) * scale);
            mx1 = fmaxf(mx1, fmaxf(sacc[nt][2], sacc[nt][3]) * scale);
        }
        mx0 = fmaxf(mx0, __shfl_xor_sync(0xffffffff, mx0, 1));
        mx0 = fmaxf(mx0, __shfl_xor_sync(0xffffffff, mx0, 2));
        mx1 = fmaxf(mx1, __shfl_xor_sync(0xffffffff, mx1, 1));
        mx1 = fmaxf(mx1, __shfl_xor_sync(0xffffffff, mx1, 2));
        float al0 = __expf(m_[0] - mx0);
        float al1 = __expf(m_[1] - mx1);
        m_[0] = mx0; m_[1] = mx1;

        uint32_t pf[8][2];
        float rs0 = 0.f, rs1 = 0.f;
#pragma unroll
        for (int nt = 0; nt < 8; nt++) {
            float p0 = __expf(sacc[nt][0] * scale - mx0);
            float p1 = __expf(sacc[nt][1] * scale - mx0);
            float p2 = __expf(sacc[nt][2] * scale - mx1);
            float p3 = __expf(sacc[nt][3] * scale - mx1);
            rs0 += p0 + p1; rs1 += p2 + p3;
            pf[nt][0] = packh2(p0, p1);
            pf[nt][1] = packh2(p2, p3);
        }
        rs0 += __shfl_xor_sync(0xffffffff, rs0, 1);
        rs0 += __shfl_xor_sync(0xffffffff, rs0, 2);
        rs1 += __shfl_xor_sync(0xffffffff, rs1, 1);
        rs1 += __shfl_xor_sync(0xffffffff, rs1, 2);
        l_[0] = l_[0] * al0 + rs0;
        l_[1] = l_[1] * al1 + rs1;

#pragma unroll
        for (int nt = 0; nt < 16; nt++) {
            oacc[nt][0] *= al0; oacc[nt][1] *= al0;
            oacc[nt][2] *= al1; oacc[nt][3] *= al1;
        }

        // ---- O += P(fp16) @ V(fp16) ----
#pragma unroll
        for (int kc = 0; kc < 4; kc++) {
            uint32_t ah[4] = {pf[2 * kc][0], pf[2 * kc][1], pf[2 * kc + 1][0], pf[2 * kc + 1][1]};
#pragma unroll
            for (int dh = 0; dh < 2; dh++) {
                uint32_t vb_[4][4];
#pragma unroll
                for (int ng = 0; ng < 4; ng++) {
                    int cbase = dh * 64 + ng * 16;
                    ldsm_x4_t(vb_[ng], smem_u32(sV + (kc * 16 + vrow) * FQS + cbase + vcol));
                }
#pragma unroll
                for (int nt = 0; nt < 8; nt++) {
                    int np = nt >> 1, hf = (nt & 1) * 2;
                    mma_f16(oacc[dh * 8 + nt], ah, vb_[np][hf], vb_[np][hf + 1]);
                }
            }
        }
        __syncthreads();
        issue_kv(kt + 3);
    }

    // ---- epilogue: normalize, split to bf16 hi/lo, store ----
    float inv0 = 1.f / (l_[0] + 1e-10f);
    float inv1 = 1.f / (l_[1] + 1e-10f);
    const int c2 = (lane & 3) * 2;
    const size_t ob = ((size_t)(b * S_ + qt * 64 + wid * 16 + g)) * QW_ + (size_t)h * HD_;
#pragma unroll
    for (int nt = 0; nt < 16; nt++) {
        int col = nt * 8 + c2;
        uint32_t h0, l0, h1, l1;
        split2(oacc[nt][0] * inv0, oacc[nt][1] * inv0, h0, l0);
        split2(oacc[nt][2] * inv1, oacc[nt][3] * inv1, h1, l1);
        *(uint32_t*)&Oh_g[ob + col] = h0;
        *(uint32_t*)&Ol_g[ob + col] = l0;
        *(uint32_t*)&Oh_g[ob + 8 * QW_ + col] = h1;
        *(uint32_t*)&Ol_g[ob + 8 * QW_ + col] = l1;
    }
}

// ---------------------------------------------------------------------------
// Launch (5 launches; flash at index 3 for ncu's skip window)
// ---------------------------------------------------------------------------
extern "C" void kernel_launch(void* const* d_in, const int* in_sizes, int n_in,
                              void* d_out, int out_size) {
    const float* X   = (const float*)d_in[0];
    const float* q_w = (const float*)d_in[1];
    const float* q_b = (const float*)d_in[2];
    const float* k_w = (const float*)d_in[3];
    const float* k_b = (const float*)d_in[4];
    const float* v_w = (const float*)d_in[5];
    const float* v_b = (const float*)d_in[6];
    const float* o_w = (const float*)d_in[7];
    const float* o_b = (const float*)d_in[8];
    float* out = (float*)d_out;

    float *pQKVf, *pqkvb;
    bf16 *pXh, *pXl, *pwh, *pwl, *powh, *powl, *pAh, *pAl;
    fp16 *pQ16, *pK16, *pV16;
    cudaGetSymbolAddress((void**)&pQKVf, g_QKVf);
    cudaGetSymbolAddress((void**)&pqkvb, g_qkvb);
    cudaGetSymbolAddress((void**)&pXh, g_Xh);   cudaGetSymbolAddress((void**)&pXl, g_Xl);
    cudaGetSymbolAddress((void**)&pwh, g_wh);   cudaGetSymbolAddress((void**)&pwl, g_wl);
    cudaGetSymbolAddress((void**)&powh, g_owh); cudaGetSymbolAddress((void**)&powl, g_owl);
    cudaGetSymbolAddress((void**)&pAh, g_Ah);   cudaGetSymbolAddress((void**)&pAl, g_Al);
    cudaGetSymbolAddress((void**)&pQ16, g_Q16);
    cudaGetSymbolAddress((void**)&pK16, g_K16); cudaGetSymbolAddress((void**)&pV16, g_V16);

    cudaFuncSetAttribute(gemm_tc3, cudaFuncAttributeMaxDynamicSharedMemorySize, GEMM_SMEM);
    cudaFuncSetAttribute(flash_fp16, cudaFuncAttributeMaxDynamicSharedMemorySize, FA_SMEM);

    // launch 0: tables + splits + bias
    prep_all_kernel<<<(PREP_TOTAL + 255) / 256, 256>>>(X, q_w, k_w, v_w, o_w, q_b, k_b, v_b);
    // launch 1: fused QKV projection
    gemm_tc3<<<dim3(QKVW_ / 128, M_ / 128), 256, GEMM_SMEM>>>(
        pXh, pXl, pwh, pwl, pqkvb, pQKVf, M_, QKVW_, H_);
    // launch 2: RoPE Q/K + V convert
    rope_all_kernel<<<(ROPE_TOTAL + 255) / 256, 256>>>(pQKVf, pQ16, pK16, pV16);
    // launch 3: flash attention
    flash_fp16<<<dim3(S_ / 64, NH_, B_), 128, FA_SMEM>>>(
        pQ16, pK16, pV16, pAh, pAl);
    // launch 4: output projection
    gemm_tc3<<<dim3(H_ / 128, M_ / 128), 256, GEMM_SMEM>>>(
        pAh, pAl, powh, powl, o_b, out, M_, H_, H_);
}

// round 8
// speedup vs baseline: 9.4590x; 1.8401x over previous
#include <cuda_runtime.h>
#include <cuda_bf16.h>
#include <cuda_fp16.h>
#include <math.h>
#include <stdint.h>

typedef __half fp16;

// Problem constants
#define B_    2
#define S_    2048
#define H_    2048
#define NH_   16
#define NKV_  4
#define HD_   128
#define M_    (B_ * S_)          // 4096
#define QW_   (NH_ * HD_)        // 2048
#define KVW_  (NKV_ * HD_)       // 512
#define NREP_ (NH_ / NKV_)       // 4
#define QKVW_ 3072

// ---------------------------------------------------------------------------
// Scratch device globals
// ---------------------------------------------------------------------------
__device__ float g_QKVf[(size_t)M_ * QKVW_];   // fused projection out (fp32)
__device__ float g_qkvb[QKVW_];
__device__ fp16 g_X16[(size_t)M_ * H_];
__device__ fp16 g_w16[(size_t)QKVW_ * H_];     // merged qkv weights
__device__ fp16 g_ow16[(size_t)H_ * QW_];
__device__ fp16 g_Q16[(size_t)M_ * QW_];       // roped Q
__device__ fp16 g_K16[(size_t)M_ * KVW_];      // roped K
__device__ fp16 g_V16[(size_t)M_ * KVW_];
__device__ fp16 g_A16[(size_t)M_ * QW_];       // attention out
__device__ float g_cosT[S_ * 64];
__device__ float g_sinT[S_ * 64];

// ---------------------------------------------------------------------------
// Helpers
// ---------------------------------------------------------------------------
__device__ __forceinline__ uint32_t smem_u32(const void* p) {
    return (uint32_t)__cvta_generic_to_shared(p);
}
__device__ __forceinline__ void ldsm_x4(uint32_t* r, uint32_t a) {
    asm volatile("ldmatrix.sync.aligned.m8n8.x4.shared.b16 {%0,%1,%2,%3},[%4];"
        : "=r"(r[0]), "=r"(r[1]), "=r"(r[2]), "=r"(r[3]) : "r"(a));
}
__device__ __forceinline__ void ldsm_x4_t(uint32_t* r, uint32_t a) {
    asm volatile("ldmatrix.sync.aligned.m8n8.x4.trans.shared.b16 {%0,%1,%2,%3},[%4];"
        : "=r"(r[0]), "=r"(r[1]), "=r"(r[2]), "=r"(r[3]) : "r"(a));
}
__device__ __forceinline__ void mma_f16(float* c, const uint32_t* a, uint32_t b0, uint32_t b1) {
    asm volatile(
        "mma.sync.aligned.m16n8k16.row.col.f32.f16.f16.f32 "
        "{%0,%1,%2,%3},{%4,%5,%6,%7},{%8,%9},{%0,%1,%2,%3};"
        : "+f"(c[0]), "+f"(c[1]), "+f"(c[2]), "+f"(c[3])
        : "r"(a[0]), "r"(a[1]), "r"(a[2]), "r"(a[3]), "r"(b0), "r"(b1));
}
__device__ __forceinline__ uint32_t packh2(float a, float b) {
    __half2 h = __floats2half2_rn(a, b);
    return *reinterpret_cast<uint32_t*>(&h);
}
__device__ __forceinline__ void cp16(void* dst, const void* src) {
    uint32_t d = smem_u32(dst);
    asm volatile("cp.async.cg.shared.global [%0],[%1],16;" :: "r"(d), "l"(src));
}
__device__ __forceinline__ void cp_commit() {
    asm volatile("cp.async.commit_group;");
}
template <int N> __device__ __forceinline__ void cp_wait() {
    asm volatile("cp.async.wait_group %0;" :: "n"(N));
}

// ---------------------------------------------------------------------------
// Prep 0: RoPE tables (double precision)
// ---------------------------------------------------------------------------
__global__ void rope_tables_kernel() {
    int idx = blockIdx.x * blockDim.x + threadIdx.x;
    if (idx >= S_ * 64) return;
    int s = idx >> 6, j = idx & 63;
    double inv_freq = exp(-((double)j / 64.0) * log(10000.0));
    double ang = (double)s * inv_freq;
    g_cosT[idx] = (float)cos(ang);
    g_sinT[idx] = (float)sin(ang);
}

// ---------------------------------------------------------------------------
// Prep 1: X -> fp16
// ---------------------------------------------------------------------------
__global__ void conv_x_kernel(const float* __restrict__ X, int n4) {
    int i = blockIdx.x * blockDim.x + threadIdx.x;
    if (i >= n4) return;
    float4 v = ((const float4*)X)[i];
    uint2 o;
    o.x = packh2(v.x, v.y);
    o.y = packh2(v.z, v.w);
    ((uint2*)g_X16)[i] = o;
}

// ---------------------------------------------------------------------------
// Prep 2: weights -> fp16 (merged qkv + o) and bias concat
// ---------------------------------------------------------------------------
#define NW_QW (QW_ * H_ / 4)
#define NW_KW (KVW_ * H_ / 4)
#define NW_VW (KVW_ * H_ / 4)
#define NW_OW (H_ * QW_ / 4)
#define W1 (NW_QW)
#define W2 (W1 + NW_KW)
#define W3 (W2 + NW_VW)
#define W4 (W3 + NW_OW)
#define W5 (W4 + QKVW_ / 4)

__global__ void conv_w_kernel(const float* __restrict__ qw, const float* __restrict__ kw,
                              const float* __restrict__ vw, const float* __restrict__ ow,
                              const float* __restrict__ qb, const float* __restrict__ kb,
                              const float* __restrict__ vb) {
    int i = blockIdx.x * blockDim.x + threadIdx.x;
    if (i >= W5) return;
    const float* src;
    fp16* dst;
    int off;
    if (i < W1)      { src = qw; dst = g_w16;                       off = i; }
    else if (i < W2) { src = kw; dst = g_w16 + (size_t)2048 * H_;   off = i - W1; }
    else if (i < W3) { src = vw; dst = g_w16 + (size_t)2560 * H_;   off = i - W2; }
    else if (i < W4) { src = ow; dst = g_ow16;                      off = i - W3; }
    else {
        int j = (i - W4) * 4;
#pragma unroll
        for (int t = 0; t < 4; t++) {
            int c = j + t;
            g_qkvb[c] = (c < 2048) ? qb[c] : (c < 2560 ? kb[c - 2048] : vb[c - 2560]);
        }
        return;
    }
    float4 v = ((const float4*)src)[off];
    uint2 o;
    o.x = packh2(v.x, v.y);
    o.y = packh2(v.z, v.w);
    ((uint2*)dst)[off] = o;
}

// ---------------------------------------------------------------------------
// Prep 4 (after QKV gemm): RoPE Q + RoPE K + V convert, one launch
// ---------------------------------------------------------------------------
#define RQ_TOTAL (M_ * NH_ * 64)
#define RK_TOTAL (M_ * NKV_ * 64)
#define VH_TOTAL (M_ * 512 / 4)
#define ROPE_TOTAL (RQ_TOTAL + RK_TOTAL + VH_TOTAL)

__global__ void rope_all_kernel(const float* __restrict__ QKVf,
                                fp16* __restrict__ Q16, fp16* __restrict__ K16,
                                fp16* __restrict__ V16) {
    int idx = blockIdx.x * blockDim.x + threadIdx.x;
    if (idx < RQ_TOTAL) {
        int j = idx & 63;
        int t = idx >> 6;
        int h = t % NH_;
        int row = t / NH_;
        int s = row & (S_ - 1);
        float c  = g_cosT[s * 64 + j];
        float sn = g_sinT[s * 64 + j];
        size_t ib = (size_t)row * QKVW_ + h * HD_;
        size_t ob = (size_t)row * QW_ + h * HD_;
        float x1 = QKVf[ib + j];
        float x2 = QKVf[ib + j + 64];
        Q16[ob + j]      = __float2half_rn(x1 * c - x2 * sn);
        Q16[ob + j + 64] = __float2half_rn(x2 * c + x1 * sn);
    } else if (idx < RQ_TOTAL + RK_TOTAL) {
        int id = idx - RQ_TOTAL;
        int j = id & 63;
        int t = id >> 6;
        int h = t % NKV_;
        int row = t / NKV_;
        int s = row & (S_ - 1);
        float c  = g_cosT[s * 64 + j];
        float sn = g_sinT[s * 64 + j];
        size_t ib = (size_t)row * QKVW_ + 2048 + h * HD_;
        size_t ob = (size_t)row * KVW_ + h * HD_;
        float x1 = QKVf[ib + j];
        float x2 = QKVf[ib + j + 64];
        K16[ob + j]      = __float2half_rn(x1 * c - x2 * sn);
        K16[ob + j + 64] = __float2half_rn(x2 * c + x1 * sn);
    } else if (idx < ROPE_TOTAL) {
        int i = idx - RQ_TOTAL - RK_TOTAL;
        int row = i >> 7;
        int c4 = (i & 127) * 4;
        float4 v = *(const float4*)&QKVf[(size_t)row * QKVW_ + 2560 + c4];
        uint2 o;
        o.x = packh2(v.x, v.y);
        o.y = packh2(v.z, v.w);
        *(uint2*)&V16[(size_t)row * KVW_ + c4] = o;
    }
}

// ---------------------------------------------------------------------------
// GEMM, single fp16 mma: C[M,N] = A[M,K] @ W[N,K]^T + bias (fp32 out)
// BM=BN=128, BK=64, 256 threads (8 warps 2x4, warp tile 64x32),
// 3-stage cp.async ring, 2 CTAs/SM.
// ---------------------------------------------------------------------------
#define GS 72                      // smem row stride (fp16): 64 + 8 pad
#define GTILE (128 * GS)           // one tile (elems)
#define GSTG (2 * GTILE)           // A + B per stage
#define GEMM_SMEM (3 * GSTG * 2)   // bytes = 110592

__global__ __launch_bounds__(256, 2)
void gemm_f16(const fp16* __restrict__ Ag, const fp16* __restrict__ Bg,
              const float* __restrict__ bias, float* __restrict__ C,
              int M, int N, int K) {
    extern __shared__ fp16 smg[];

    const int tid = threadIdx.x;
    const int lane = tid & 31, wid = tid >> 5;
    const int wm = wid >> 2, wn = wid & 3;
    const int bm = blockIdx.y * 128, bn = blockIdx.x * 128;

    const int arow = (lane & 7) + ((lane >> 3) & 1) * 8;
    const int acol = ((lane >> 4) & 1) * 8;
    const int brow = (lane & 7) + ((lane >> 4) & 1) * 8;
    const int bcol = ((lane >> 3) & 1) * 8;

    float acc[4][4][4];
#pragma unroll
    for (int i = 0; i < 4; i++)
#pragma unroll
        for (int j = 0; j < 4; j++)
#pragma unroll
            for (int k = 0; k < 4; k++) acc[i][j][k] = 0.f;

    const int nIter = K / 64;

    auto issue_stage = [&](int t) {
        if (t < nIter) {
            const int k0 = t * 64;
            fp16* sb = smg + (t % 3) * GSTG;
#pragma unroll
            for (int i = 0; i < 8; i++) {
                int id = i * 256 + tid;          // 0..2047
                int tile = id >> 10;             // 0:A 1:B
                int rem = id & 1023;
                int r = rem >> 3, ch = rem & 7;
                const fp16* src = (tile ? Bg + (size_t)(bn + r) * K
                                        : Ag + (size_t)(bm + r) * K) + k0 + ch * 8;
                cp16(sb + tile * GTILE + r * GS + ch * 8, src);
            }
        }
        cp_commit();
    };

    issue_stage(0);
    issue_stage(1);

    for (int t = 0; t < nIter; t++) {
        cp_wait<1>();
        __syncthreads();
        issue_stage(t + 2);

        const fp16* pA = smg + (t % 3) * GSTG;
        const fp16* pB = pA + GTILE;

#pragma unroll
        for (int kk = 0; kk < 64; kk += 16) {
            uint32_t fa[4][4], fb[2][4];
#pragma unroll
            for (int mt = 0; mt < 4; mt++) {
                int r = wm * 64 + mt * 16 + arow;
                ldsm_x4(fa[mt], smem_u32(pA + r * GS + kk + acol));
            }
#pragma unroll
            for (int np = 0; np < 2; np++) {
                int r = wn * 32 + np * 16 + brow;
                ldsm_x4(fb[np], smem_u32(pB + r * GS + kk + bcol));
            }
#pragma unroll
            for (int mt = 0; mt < 4; mt++) {
#pragma unroll
                for (int nt = 0; nt < 4; nt++) {
                    int np = nt >> 1, hf = (nt & 1) * 2;
                    mma_f16(acc[mt][nt], fa[mt], fb[np][hf], fb[np][hf + 1]);
                }
            }
        }
    }

    const int g = lane >> 2, c2 = (lane & 3) * 2;
#pragma unroll
    for (int mt = 0; mt < 4; mt++) {
        int row = bm + wm * 64 + mt * 16 + g;
#pragma unroll
        for (int nt = 0; nt < 4; nt++) {
            int col = bn + wn * 32 + nt * 8 + c2;
            float b0 = bias[col], b1 = bias[col + 1];
            *(float2*)&C[(size_t)row * N + col] =
                make_float2(acc[mt][nt][0] + b0, acc[mt][nt][1] + b1);
            *(float2*)&C[(size_t)(row + 8) * N + col] =
                make_float2(acc[mt][nt][2] + b0, acc[mt][nt][3] + b1);
        }
    }
}

// ---------------------------------------------------------------------------
// Flash attention: 128 threads (4 warps x 16 q-rows), Q fragments via LDG,
// 3-stage KV cp.async ring, 2 CTAs/SM, single-fp16 mma. fp16 output.
// ---------------------------------------------------------------------------
#define FQS 136
#define FKV_TILE (64 * FQS)
#define FKV_STAGE (2 * FKV_TILE)
#define FA_NSTAGE 3
#define FA_SMEM (FA_NSTAGE * FKV_STAGE * 2)   // 104448 B

__global__ __launch_bounds__(128, 2)
void flash_fp16(const fp16* __restrict__ Q_g,
                const fp16* __restrict__ K_g, const fp16* __restrict__ V_g,
                fp16* __restrict__ O_g) {
    extern __shared__ fp16 smf[];
    fp16* stage0 = smf;

    const int tid = threadIdx.x, lane = tid & 31, wid = tid >> 5;
    const int qt = blockIdx.x, h = blockIdx.y, b = blockIdx.z;
    const int kvh = h / NREP_;
    const float scale = 0.08838834764831845f;

    const int g = lane >> 2;
    const int brow = (lane & 7) + ((lane >> 4) & 1) * 8;
    const int bcol = ((lane >> 3) & 1) * 8;
    const int vrow = (lane & 7) + ((lane >> 3) & 1) * 8;
    const int vcol = ((lane >> 4) & 1) * 8;

    auto issue_kv = [&](int kt) {
        if (kt < S_ / 64) {
            const size_t kb = ((size_t)(b * S_ + kt * 64)) * KVW_ + (size_t)kvh * HD_;
            fp16* sb = stage0 + (kt % FA_NSTAGE) * FKV_STAGE;
#pragma unroll
            for (int i = 0; i < 16; i++) {
                int id = i * 128 + tid;
                int tile = id >> 10;       // 0:K 1:V
                int rem = id & 1023;
                int r = rem >> 4, ch = rem & 15;
                const fp16* src = (tile ? V_g : K_g) + kb + (size_t)r * KVW_ + ch * 8;
                cp16(sb + tile * FKV_TILE + r * FQS + ch * 8, src);
            }
        }
        cp_commit();
    };
    issue_kv(0);
    issue_kv(1);
    issue_kv(2);

    // ---- Q fragments: direct LDG from global in mma layout ----
    const size_t qb = ((size_t)(b * S_ + qt * 64)) * QW_ + (size_t)h * HD_;
    uint32_t qf[8][4];
    {
        const int r0 = wid * 16 + g;
        const int c0 = (lane & 3) * 2;
#pragma unroll
        for (int kc = 0; kc < 8; kc++) {
#pragma unroll
            for (int i = 0; i < 4; i++) {
                int r = r0 + (i & 1) * 8;
                int c = kc * 16 + c0 + (i >> 1) * 8;
                qf[kc][i] = *(const uint32_t*)&Q_g[qb + (size_t)r * QW_ + c];
            }
        }
    }

    float m_[2] = {-INFINITY, -INFINITY};
    float l_[2] = {0.f, 0.f};
    float oacc[16][4];
#pragma unroll
    for (int i = 0; i < 16; i++)
#pragma unroll
        for (int j = 0; j < 4; j++) oacc[i][j] = 0.f;

    const int NT = S_ / 64;
    for (int kt = 0; kt < NT; kt++) {
        cp_wait<2>();
        __syncthreads();

        const fp16* sK = stage0 + (kt % FA_NSTAGE) * FKV_STAGE;
        const fp16* sV = sK + FKV_TILE;

        // ---- S = Q @ K^T ----
        float sacc[8][4];
#pragma unroll
        for (int i = 0; i < 8; i++)
#pragma unroll
            for (int j = 0; j < 4; j++) sacc[i][j] = 0.f;

#pragma unroll
        for (int kc = 0; kc < 8; kc++) {
            uint32_t kb_[4][4];
#pragma unroll
            for (int ng = 0; ng < 4; ng++) {
                int r = ng * 16 + brow;
                ldsm_x4(kb_[ng], smem_u32(sK + r * FQS + kc * 16 + bcol));
            }
#pragma unroll
            for (int nt = 0; nt < 8; nt++) {
                int np = nt >> 1, hf = (nt & 1) * 2;
                mma_f16(sacc[nt], qf[kc], kb_[np][hf], kb_[np][hf + 1]);
            }
        }

        // ---- online softmax ----
        float mx0 = m_[0], mx1 = m_[1];
#pragma unroll
        for (int nt = 0; nt < 8; nt++) {
            mx0 = fmaxf(mx0, fmaxf(sacc[nt][0], sacc[nt][1]) * scale);
            mx1 = fmaxf(mx1, fmaxf(sacc[nt][2], sacc[nt][3]) * scale);
        }
        mx0 = fmaxf(mx0, __shfl_xor_sync(0xffffffff, mx0, 1));
        mx0 = fmaxf(mx0, __shfl_xor_sync(0xffffffff, mx0, 2));
        mx1 = fmaxf(mx1, __shfl_xor_sync(0xffffffff, mx1, 1));
        mx1 = fmaxf(mx1, __shfl_xor_sync(0xffffffff, mx1, 2));
        float al0 = __expf(m_[0] - mx0);
        float al1 = __expf(m_[1] - mx1);
        m_[0] = mx0; m_[1] = mx1;

        uint32_t pf[8][2];
        float rs0 = 0.f, rs1 = 0.f;
#pragma unroll
        for (int nt = 0; nt < 8; nt++) {
            float p0 = __expf(sacc[nt][0] * scale - mx0);
            float p1 = __expf(sacc[nt][1] * scale - mx0);
            float p2 = __expf(sacc[nt][2] * scale - mx1);
            float p3 = __expf(sacc[nt][3] * scale - mx1);
            rs0 += p0 + p1; rs1 += p2 + p3;
            pf[nt][0] = packh2(p0, p1);
            pf[nt][1] = packh2(p2, p3);
        }
        rs0 += __shfl_xor_sync(0xffffffff, rs0, 1);
        rs0 += __shfl_xor_sync(0xffffffff, rs0, 2);
        rs1 += __shfl_xor_sync(0xffffffff, rs1, 1);
        rs1 += __shfl_xor_sync(0xffffffff, rs1, 2);
        l_[0] = l_[0] * al0 + rs0;
        l_[1] = l_[1] * al1 + rs1;

#pragma unroll
        for (int nt = 0; nt < 16; nt++) {
            oacc[nt][0] *= al0; oacc[nt][1] *= al0;
            oacc[nt][2] *= al1; oacc[nt][3] *= al1;
        }

        // ---- O += P @ V ----
#pragma unroll
        for (int kc = 0; kc < 4; kc++) {
            uint32_t ah[4] = {pf[2 * kc][0], pf[2 * kc][1], pf[2 * kc + 1][0], pf[2 * kc + 1][1]};
#pragma unroll
            for (int dh = 0; dh < 2; dh++) {
                uint32_t vb_[4][4];
#pragma unroll
                for (int ng = 0; ng < 4; ng++) {
                    int cbase = dh * 64 + ng * 16;
                    ldsm_x4_t(vb_[ng], smem_u32(sV + (kc * 16 + vrow) * FQS + cbase + vcol));
                }
#pragma unroll
                for (int nt = 0; nt < 8; nt++) {
                    int np = nt >> 1, hf = (nt & 1) * 2;
                    mma_f16(oacc[dh * 8 + nt], ah, vb_[np][hf], vb_[np][hf + 1]);
                }
            }
        }
        __syncthreads();
        issue_kv(kt + 3);
    }

    // ---- epilogue: normalize, store fp16 ----
    float inv0 = 1.f / (l_[0] + 1e-10f);
    float inv1 = 1.f / (l_[1] + 1e-10f);
    const int c2 = (lane & 3) * 2;
    const size_t ob = ((size_t)(b * S_ + qt * 64 + wid * 16 + g)) * QW_ + (size_t)h * HD_;
#pragma unroll
    for (int nt = 0; nt < 16; nt++) {
        int col = nt * 8 + c2;
        *(uint32_t*)&O_g[ob + col] = packh2(oacc[nt][0] * inv0, oacc[nt][1] * inv0);
        *(uint32_t*)&O_g[ob + 8 * QW_ + col] = packh2(oacc[nt][2] * inv1, oacc[nt][3] * inv1);
    }
}

// ---------------------------------------------------------------------------
// Launch — 7 launches; index 3 (ncu's window) = QKV GEMM
// ---------------------------------------------------------------------------
extern "C" void kernel_launch(void* const* d_in, const int* in_sizes, int n_in,
                              void* d_out, int out_size) {
    const float* X   = (const float*)d_in[0];
    const float* q_w = (const float*)d_in[1];
    const float* q_b = (const float*)d_in[2];
    const float* k_w = (const float*)d_in[3];
    const float* k_b = (const float*)d_in[4];
    const float* v_w = (const float*)d_in[5];
    const float* v_b = (const float*)d_in[6];
    const float* o_w = (const float*)d_in[7];
    const float* o_b = (const float*)d_in[8];
    float* out = (float*)d_out;

    float *pQKVf, *pqkvb;
    fp16 *pX16, *pw16, *pow16, *pQ16, *pK16, *pV16, *pA16;
    cudaGetSymbolAddress((void**)&pQKVf, g_QKVf);
    cudaGetSymbolAddress((void**)&pqkvb, g_qkvb);
    cudaGetSymbolAddress((void**)&pX16, g_X16);
    cudaGetSymbolAddress((void**)&pw16, g_w16);
    cudaGetSymbolAddress((void**)&pow16, g_ow16);
    cudaGetSymbolAddress((void**)&pQ16, g_Q16);
    cudaGetSymbolAddress((void**)&pK16, g_K16);
    cudaGetSymbolAddress((void**)&pV16, g_V16);
    cudaGetSymbolAddress((void**)&pA16, g_A16);

    cudaFuncSetAttribute(gemm_f16, cudaFuncAttributeMaxDynamicSharedMemorySize, GEMM_SMEM);
    cudaFuncSetAttribute(flash_fp16, cudaFuncAttributeMaxDynamicSharedMemorySize, FA_SMEM);

    // launch 0: RoPE tables
    rope_tables_kernel<<<(S_ * 64 + 255) / 256, 256>>>();
    // launch 1: X -> fp16
    conv_x_kernel<<<((M_ * H_ / 4) + 255) / 256, 256>>>(X, M_ * H_ / 4);
    // launch 2: weights -> fp16 + bias
    conv_w_kernel<<<(W5 + 255) / 256, 256>>>(q_w, k_w, v_w, o_w, q_b, k_b, v_b);
    // launch 3: fused QKV projection  <- ncu window
    gemm_f16<<<dim3(QKVW_ / 128, M_ / 128), 256, GEMM_SMEM>>>(
        pX16, pw16, pqkvb, pQKVf, M_, QKVW_, H_);
    // launch 4: RoPE Q/K + V convert
    rope_all_kernel<<<(ROPE_TOTAL + 255) / 256, 256>>>(pQKVf, pQ16, pK16, pV16);
    // launch 5: flash attention
    flash_fp16<<<dim3(S_ / 64, NH_, B_), 128, FA_SMEM>>>(
        pQ16, pK16, pV16, pA16);
    // launch 6: output projection
    gemm_f16<<<dim3(H_ / 128, M_ / 128), 256, GEMM_SMEM>>>(
        pA16, pow16, o_b, out, M_, H_, H_);
}